// round 10
// baseline (speedup 1.0000x reference)
#include <cuda_runtime.h>
#include <cuda_bf16.h>

#define MM   64
#define HH   128
#define INF_ 3
#define AA   64
#define NT   512

#define SH_STR 136   // bf16 units; 272B row stride (== 16 mod 128)
#define AT_STR 68    // bf16 units; 136B row stride (== 8 mod 128)
#define WT_STR 68    // bf16 units; 136B row stride

typedef __nv_bfloat16 bf16;
typedef unsigned int uint;

__device__ float g_c2l[HH], g_c2r[HH], g_c1l[INF_], g_c1r[INF_];
// W2 pre-split (hi/lo bf16), m16n8k16 B-fragment order:
// idx = (((ks*16 + nu)*32 + lane)*2 + w); k = ks*16 + 2*(lane&3) + 8*w, n = nu*8 + (lane>>2)
__device__ uint g_W2Bhi[8 * 16 * 32 * 2];
__device__ uint g_W2Blo[8 * 16 * 32 * 2];

__device__ __forceinline__ uint packbf(bf16 a, bf16 b) {
    __nv_bfloat162 v = __halves2bfloat162(a, b);
    return *(uint*)&v;
}

__device__ __forceinline__ void mma16816(float4& d, uint a0, uint a1, uint a2, uint a3,
                                         uint b0, uint b1) {
    asm volatile(
        "mma.sync.aligned.m16n8k16.row.col.f32.bf16.bf16.f32 "
        "{%0,%1,%2,%3}, {%4,%5,%6,%7}, {%8,%9}, {%0,%1,%2,%3};"
        : "+f"(d.x), "+f"(d.y), "+f"(d.z), "+f"(d.w)
        : "r"(a0), "r"(a1), "r"(a2), "r"(a3), "r"(b0), "r"(b1));
}

__device__ __forceinline__ void storeSplit(bf16* hi, bf16* lo, int idx, float v) {
    bf16 h = __float2bfloat16_rn(v);
    hi[idx] = h;
    lo[idx] = __float2bfloat16_rn(v - __bfloat162float(h));
}

__global__ void precomp_kernel(const float* __restrict__ W1, const float* __restrict__ a1,
                               const float* __restrict__ W2, const float* __restrict__ a2) {
    int t = threadIdx.x;  // 128 threads
    float s1 = 0.f, s2 = 0.f;
#pragma unroll 8
    for (int j = 0; j < HH; j++) {
        float w = W2[t * HH + j];
        s1 = fmaf(w, a2[j], s1);
        s2 = fmaf(w, a2[HH + j], s2);
    }
    g_c2l[t] = s1;
    g_c2r[t] = s2;
    if (t < INF_) {
        float p = 0.f, q = 0.f;
#pragma unroll 8
        for (int j = 0; j < HH; j++) {
            float w = W1[t * HH + j];
            p = fmaf(w, a1[j], p);
            q = fmaf(w, a1[HH + j], q);
        }
        g_c1l[t] = p;
        g_c1r[t] = q;
    }
    for (int idx = t; idx < 8 * 16 * 32 * 2; idx += 128) {
        int w = idx & 1;
        int lane = (idx >> 1) & 31;
        int nu = (idx >> 6) & 15;
        int ks = idx >> 10;
        int g = lane >> 2, tt = lane & 3;
        int k = ks * 16 + 2 * tt + 8 * w;
        int n = nu * 8 + g;
        float v0 = W2[k * HH + n];
        float v1 = W2[(k + 1) * HH + n];
        bf16 h0 = __float2bfloat16_rn(v0);
        bf16 h1 = __float2bfloat16_rn(v1);
        g_W2Bhi[idx] = packbf(h0, h1);
        g_W2Blo[idx] = packbf(__float2bfloat16_rn(v0 - __bfloat162float(h0)),
                              __float2bfloat16_rn(v1 - __bfloat162float(h1)));
    }
}

__device__ __forceinline__ void softmax64_bf(char* __restrict__ atHi, char* __restrict__ atLo,
                                             const float* __restrict__ sSi,
                                             const float* __restrict__ sSj, int tid) {
    int row = tid >> 3, l8 = tid & 7;
    float si = sSi[row];
    const float* sj = sSj + l8 * 8;
    float ev[8];
    float m = -1e30f;
#pragma unroll
    for (int j = 0; j < 8; j++) {
        float x = si + sj[j];
        x = (x > 0.f) ? x : 0.2f * x;
        ev[j] = x;
        m = fmaxf(m, x);
    }
    m = fmaxf(m, __shfl_xor_sync(0xffffffffu, m, 1));
    m = fmaxf(m, __shfl_xor_sync(0xffffffffu, m, 2));
    m = fmaxf(m, __shfl_xor_sync(0xffffffffu, m, 4));
    float s = 0.f;
#pragma unroll
    for (int j = 0; j < 8; j++) {
        float e = __expf(ev[j] - m);
        ev[j] = e;
        s += e;
    }
    s += __shfl_xor_sync(0xffffffffu, s, 1);
    s += __shfl_xor_sync(0xffffffffu, s, 2);
    s += __shfl_xor_sync(0xffffffffu, s, 4);
    float inv = 1.0f / s;
    uint* dh = (uint*)(atHi + row * (AT_STR * 2) + l8 * 16);
    uint* dl = (uint*)(atLo + row * (AT_STR * 2) + l8 * 16);
#pragma unroll
    for (int p = 0; p < 4; p++) {
        float v0 = ev[2 * p] * inv, v1 = ev[2 * p + 1] * inv;
        bf16 h0 = __float2bfloat16_rn(v0);
        bf16 h1 = __float2bfloat16_rn(v1);
        dh[p] = packbf(h0, h1);
        dl[p] = packbf(__float2bfloat16_rn(v0 - __bfloat162float(h0)),
                       __float2bfloat16_rn(v1 - __bfloat162float(h1)));
    }
}

__device__ __forceinline__ float elu1(float x) {
    return (x > 0.f) ? x : (__expf(x) - 1.0f);
}

__global__ __launch_bounds__(NT, 3) void gat_kernel(
    const float* __restrict__ users, const float* __restrict__ W1,
    const float* __restrict__ W2,
    const float* __restrict__ mw1, const float* __restrict__ mb1,
    const float* __restrict__ mw2, const float* __restrict__ mb2,
    float* __restrict__ out, int B) {
    extern __shared__ char smb[];
    // region0 (34816 B): sH (before P5 stores) and sWt (after) ALIAS each other.
    bf16* sHhi  = (bf16*)(smb);                  // 64 x 136
    bf16* sHlo  = (bf16*)(smb + 17408);
    bf16* sWthi = (bf16*)(smb);                  // 128 x 68 (Wh2 transposed)
    bf16* sWtlo = (bf16*)(smb + 17408);
    char* atHi  = smb + 34816;                   // 64 x 68 bf16
    char* atLo  = smb + 43520;
    float* sF   = (float*)(smb + 52224);
    float* sU    = sF;              // 192
    float* sSi   = sF + 192;        // 64
    float* sSj   = sF + 256;        // 64
    float* sC2l  = sF + 320;        // 128
    float* sC2r  = sF + 448;        // 128
    float* scrA  = sF + 576;        // 512: union { sT(64x4) | sPoolQ(512) }
    float* sT    = scrA;
    float* sPoolQ= scrA;
    float* sPool = sF + 1088;       // 128
    float* sR    = sF + 1216;       // 32
    float* sO    = sF + 1248;       // 128
    float* sSum  = sF + 1376;       // 2

    const int tid  = threadIdx.x;
    const int b    = blockIdx.x;
    const int warp = tid >> 5;
    const int lane = tid & 31;
    const int mi   = warp & 3;           // m16 strip
    const int nb   = warp >> 2;          // n32 block
    const int g    = lane >> 2;
    const int t4   = lane & 3;

    // ---- P0
    if (tid < MM * INF_) sU[tid] = users[b * (MM * INF_) + tid];
    if (tid < 128) { sC2l[tid] = g_c2l[tid]; sC2r[tid] = g_c2r[tid]; }
    __syncthreads();

    // ---- P1: layer1 si/sj via c1 trick
    if (tid < MM) {
        float u0 = sU[tid * 3], u1 = sU[tid * 3 + 1], u2 = sU[tid * 3 + 2];
        sSi[tid] = u0 * g_c1l[0] + u1 * g_c1l[1] + u2 * g_c1l[2];
        sSj[tid] = u0 * g_c1r[0] + u1 * g_c1r[1] + u2 * g_c1r[2];
    }
    __syncthreads();

    // ---- P2: softmax layer 1 -> attn bf16 hi/lo
    softmax64_bf(atHi, atLo, sSi, sSj, tid);
    __syncthreads();

    // ---- P3a: T = attn1 @ U (rank-3 fusion)
    {
        int row = tid >> 3, l8 = tid & 7;
        const __nv_bfloat162* ah = (const __nv_bfloat162*)(atHi + row * (AT_STR * 2) + l8 * 16);
        const __nv_bfloat162* al = (const __nv_bfloat162*)(atLo + row * (AT_STR * 2) + l8 * 16);
        float t0 = 0.f, t1 = 0.f, t2 = 0.f;
#pragma unroll
        for (int p = 0; p < 4; p++) {
            __nv_bfloat162 h2 = ah[p], l2 = al[p];
            float a0 = __bfloat162float(h2.x) + __bfloat162float(l2.x);
            float a1 = __bfloat162float(h2.y) + __bfloat162float(l2.y);
            const float* u0 = sU + (l8 * 8 + 2 * p) * 3;
            t0 = fmaf(a0, u0[0], t0); t1 = fmaf(a0, u0[1], t1); t2 = fmaf(a0, u0[2], t2);
            t0 = fmaf(a1, u0[3], t0); t1 = fmaf(a1, u0[4], t1); t2 = fmaf(a1, u0[5], t2);
        }
#pragma unroll
        for (int off = 1; off < 8; off <<= 1) {
            t0 += __shfl_xor_sync(0xffffffffu, t0, off);
            t1 += __shfl_xor_sync(0xffffffffu, t1, off);
            t2 += __shfl_xor_sync(0xffffffffu, t2, off);
        }
        if (!l8) {
            sT[row * 4 + 0] = t0;
            sT[row * 4 + 1] = t1;
            sT[row * 4 + 2] = t2;
            sT[row * 4 + 3] = 0.f;
        }
    }
    __syncthreads();

    // ---- P3b: h = elu(T @ W1), thread owns 2 adjacent cols x 8 rows -> packed STS.32
    {
        const int d2 = (tid & 63) * 2;
        const int q8 = tid >> 6;     // 0..7 -> rows q8*8..q8*8+7
        float wa0 = W1[d2],          wb0 = W1[d2 + 1];
        float wa1 = W1[HH + d2],     wb1 = W1[HH + d2 + 1];
        float wa2 = W1[2 * HH + d2], wb2 = W1[2 * HH + d2 + 1];
        uint* rh = (uint*)sHhi;
        uint* rl = (uint*)sHlo;
#pragma unroll
        for (int r = 0; r < 8; r++) {
            int row = q8 * 8 + r;
            float4 tt = *(const float4*)&sT[row * 4];
            float xa = elu1(fmaf(tt.x, wa0, fmaf(tt.y, wa1, tt.z * wa2)));
            float xb = elu1(fmaf(tt.x, wb0, fmaf(tt.y, wb1, tt.z * wb2)));
            bf16 ha = __float2bfloat16_rn(xa);
            bf16 hb = __float2bfloat16_rn(xb);
            rh[row * (SH_STR / 2) + (d2 >> 1)] = packbf(ha, hb);
            rl[row * (SH_STR / 2) + (d2 >> 1)] =
                packbf(__float2bfloat16_rn(xa - __bfloat162float(ha)),
                       __float2bfloat16_rn(xb - __bfloat162float(hb)));
        }
    }
    __syncthreads();

    // ---- P4: layer2 si/sj = h @ c2
    {
        int row = tid >> 3, l8 = tid & 7;
        const __nv_bfloat162* hh = (const __nv_bfloat162*)(sHhi + row * SH_STR + l8 * 16);
        const __nv_bfloat162* hl = (const __nv_bfloat162*)(sHlo + row * SH_STR + l8 * 16);
        const float* cl = sC2l + l8 * 16;
        const float* cr = sC2r + l8 * 16;
        float s1 = 0.f, s2 = 0.f;
#pragma unroll
        for (int p = 0; p < 8; p++) {
            __nv_bfloat162 h2 = hh[p], l2 = hl[p];
            float h0 = __bfloat162float(h2.x) + __bfloat162float(l2.x);
            float h1 = __bfloat162float(h2.y) + __bfloat162float(l2.y);
            s1 = fmaf(h0, cl[2 * p], s1);     s2 = fmaf(h0, cr[2 * p], s2);
            s1 = fmaf(h1, cl[2 * p + 1], s1); s2 = fmaf(h1, cr[2 * p + 1], s2);
        }
        s1 += __shfl_xor_sync(0xffffffffu, s1, 1);
        s2 += __shfl_xor_sync(0xffffffffu, s2, 1);
        s1 += __shfl_xor_sync(0xffffffffu, s1, 2);
        s2 += __shfl_xor_sync(0xffffffffu, s2, 2);
        s1 += __shfl_xor_sync(0xffffffffu, s1, 4);
        s2 += __shfl_xor_sync(0xffffffffu, s2, 4);
        if (!l8) { sSi[row] = s1; sSj[row] = s2; }
    }
    // ---- P5: Wh2 = h @ W2 via bf16x3 MMA; acc in regs, then aliased store
    {
        const int arow = mi * 16 + g;
        float4 acc[4];
#pragma unroll
        for (int f = 0; f < 4; f++) acc[f] = make_float4(0.f, 0.f, 0.f, 0.f);
#pragma unroll
        for (int ks = 0; ks < 8; ks++) {
            int kb = ks * 16 + 2 * t4;
            uint ah0 = *(const uint*)&sHhi[arow * SH_STR + kb];
            uint ah1 = *(const uint*)&sHhi[(arow + 8) * SH_STR + kb];
            uint ah2 = *(const uint*)&sHhi[arow * SH_STR + kb + 8];
            uint ah3 = *(const uint*)&sHhi[(arow + 8) * SH_STR + kb + 8];
            uint al0 = *(const uint*)&sHlo[arow * SH_STR + kb];
            uint al1 = *(const uint*)&sHlo[(arow + 8) * SH_STR + kb];
            uint al2 = *(const uint*)&sHlo[arow * SH_STR + kb + 8];
            uint al3 = *(const uint*)&sHlo[(arow + 8) * SH_STR + kb + 8];
#pragma unroll
            for (int f = 0; f < 4; f++) {
                int nu = nb * 4 + f;
                int bidx = ((ks * 16 + nu) * 32 + lane) * 2;
                uint2 bh = *(const uint2*)&g_W2Bhi[bidx];
                uint2 bl = *(const uint2*)&g_W2Blo[bidx];
                mma16816(acc[f], ah0, ah1, ah2, ah3, bh.x, bh.y);
                mma16816(acc[f], ah0, ah1, ah2, ah3, bl.x, bl.y);
                mma16816(acc[f], al0, al1, al2, al3, bh.x, bh.y);
            }
        }
        __syncthreads();   // all warps done READING sH -> safe to overwrite (sWt aliases sH)
#pragma unroll
        for (int f = 0; f < 4; f++) {
            int c = nb * 32 + f * 8 + 2 * t4;
            storeSplit(sWthi, sWtlo, c * WT_STR + arow,           acc[f].x);
            storeSplit(sWthi, sWtlo, (c + 1) * WT_STR + arow,     acc[f].y);
            storeSplit(sWthi, sWtlo, c * WT_STR + arow + 8,       acc[f].z);
            storeSplit(sWthi, sWtlo, (c + 1) * WT_STR + arow + 8, acc[f].w);
        }
    }
    __syncthreads();

    // ---- P6: softmax layer 2 -> attn bf16 hi/lo
    softmax64_bf(atHi, atLo, sSi, sSj, tid);
    __syncthreads();

    // ---- P7: h2 = elu(attn2 @ Wh2) via bf16x3 MMA, fused max-pool
    {
        const int arow = mi * 16 + g;
        float4 acc[4];
#pragma unroll
        for (int f = 0; f < 4; f++) acc[f] = make_float4(0.f, 0.f, 0.f, 0.f);
#pragma unroll
        for (int ks = 0; ks < 4; ks++) {
            int kb = ks * 16 + 2 * t4;
            uint ah0 = *(const uint*)(atHi + arow * (AT_STR * 2) + kb * 2);
            uint ah1 = *(const uint*)(atHi + (arow + 8) * (AT_STR * 2) + kb * 2);
            uint ah2 = *(const uint*)(atHi + arow * (AT_STR * 2) + kb * 2 + 16);
            uint ah3 = *(const uint*)(atHi + (arow + 8) * (AT_STR * 2) + kb * 2 + 16);
            uint al0 = *(const uint*)(atLo + arow * (AT_STR * 2) + kb * 2);
            uint al1 = *(const uint*)(atLo + (arow + 8) * (AT_STR * 2) + kb * 2);
            uint al2 = *(const uint*)(atLo + arow * (AT_STR * 2) + kb * 2 + 16);
            uint al3 = *(const uint*)(atLo + (arow + 8) * (AT_STR * 2) + kb * 2 + 16);
#pragma unroll
            for (int f = 0; f < 4; f++) {
                int nu = nb * 4 + f;
                uint b0h = *(const uint*)&sWthi[(nu * 8 + g) * WT_STR + kb];
                uint b1h = *(const uint*)&sWthi[(nu * 8 + g) * WT_STR + kb + 8];
                uint b0l = *(const uint*)&sWtlo[(nu * 8 + g) * WT_STR + kb];
                uint b1l = *(const uint*)&sWtlo[(nu * 8 + g) * WT_STR + kb + 8];
                mma16816(acc[f], ah0, ah1, ah2, ah3, b0h, b1h);
                mma16816(acc[f], ah0, ah1, ah2, ah3, b0l, b1l);
                mma16816(acc[f], al0, al1, al2, al3, b0h, b1h);
            }
        }
#pragma unroll
        for (int f = 0; f < 4; f++) {
            float p0 = fmaxf(elu1(acc[f].x), elu1(acc[f].z));
            float p1 = fmaxf(elu1(acc[f].y), elu1(acc[f].w));
#pragma unroll
            for (int off = 4; off < 32; off <<= 1) {
                p0 = fmaxf(p0, __shfl_xor_sync(0xffffffffu, p0, off));
                p1 = fmaxf(p1, __shfl_xor_sync(0xffffffffu, p1, off));
            }
            if (lane < 4) {
                int c = nb * 32 + f * 8 + 2 * lane;
                *(float2*)&sPoolQ[mi * 128 + c] = make_float2(p0, p1);
            }
        }
    }
    __syncthreads();

    // ---- P7b: combine the four m-strips
    if (tid < 128) {
        float p0 = sPoolQ[tid], p1 = sPoolQ[128 + tid];
        float p2 = sPoolQ[256 + tid], p3 = sPoolQ[384 + tid];
        sPool[tid] = fmaxf(fmaxf(p0, p1), fmaxf(p2, p3));
    }
    __syncthreads();

    // ---- P8: hidden = relu(pooled @ mw1 + mb1)
    if (tid < 256) {
        int col = tid >> 3, l8 = tid & 7;
        float acc = 0.f;
        const float* pp = sPool + l8 * 16;
#pragma unroll
        for (int k = 0; k < 16; k++) acc = fmaf(pp[k], mw1[(l8 * 16 + k) * 32 + col], acc);
        acc += __shfl_xor_sync(0xffffffffu, acc, 1);
        acc += __shfl_xor_sync(0xffffffffu, acc, 2);
        acc += __shfl_xor_sync(0xffffffffu, acc, 4);
        if (!l8) sR[col] = fmaxf(acc + mb1[col], 0.f);
    }
    __syncthreads();

    // ---- P9
    if (tid < 128) {
        float acc = mb2[tid];
#pragma unroll
        for (int m = 0; m < 32; m++) acc = fmaf(sR[m], mw2[m * HH + tid], acc);
        sO[tid] = fmaxf(acc, 0.f) + 1e-6f;
    }
    __syncthreads();

    // ---- P10
    if (tid < 2) {
        float s = 0.f;
        const float* p = sO + tid * 64;
#pragma unroll 8
        for (int j = 0; j < 64; j++) s += p[j];
        sSum[tid] = s;
    }
    __syncthreads();

    // ---- P11: normalize & write. power[B,A] then delta[B,A]
    if (tid < 128) {
        const float Bmax = 2.0f * 50.0f - 63.0f * 0.025f;  // 98.425
        const float PMAX = 1.0f;
        if (tid < 64) {
            out[(size_t)B * AA + (size_t)b * AA + tid] = Bmax * sO[tid] / (sSum[0] + 1e-6f);
        } else {
            out[(size_t)b * AA + (tid - 64)] = PMAX * sO[tid] / (sSum[1] + 1e-6f);
        }
    }
}

static const int SMEM_BYTES = 52224 + 1378 * 4;   // 57736

extern "C" void kernel_launch(void* const* d_in, const int* in_sizes, int n_in,
                              void* d_out, int out_size) {
    const float* users = (const float*)d_in[0];
    const float* W1    = (const float*)d_in[1];
    const float* a1    = (const float*)d_in[2];
    const float* W2    = (const float*)d_in[3];
    const float* a2    = (const float*)d_in[4];
    const float* mw1   = (const float*)d_in[5];
    const float* mb1   = (const float*)d_in[6];
    const float* mw2   = (const float*)d_in[7];
    const float* mb2   = (const float*)d_in[8];
    float* out = (float*)d_out;

    int B = in_sizes[0] / (MM * INF_);

    cudaFuncSetAttribute(gat_kernel, cudaFuncAttributeMaxDynamicSharedMemorySize, SMEM_BYTES);

    precomp_kernel<<<1, 128>>>(W1, a1, W2, a2);
    gat_kernel<<<B, NT, SMEM_BYTES>>>(users, W1, W2, mw1, mb1, mw2, mb2, out, B);
}

// round 11
// speedup vs baseline: 1.0384x; 1.0384x over previous
#include <cuda_runtime.h>
#include <cuda_bf16.h>

#define MM   64
#define HH   128
#define INF_ 3
#define AA   64
#define NT   512

#define SH_STR 136   // bf16 units; 272B row stride (== 16 mod 128)
#define AT_STR 68    // bf16 units; 136B row stride (== 8 mod 128)
#define WT_STR 68    // bf16 units; 136B row stride

typedef __nv_bfloat16 bf16;
typedef unsigned int uint;

__device__ float g_c2l[HH], g_c2r[HH], g_c1l[INF_], g_c1r[INF_];
// W2 pre-split (hi/lo bf16), m16n8k16 B-fragment order:
// idx = (((ks*16 + nu)*32 + lane)*2 + w); k = ks*16 + 2*(lane&3) + 8*w, n = nu*8 + (lane>>2)
__device__ uint g_W2Bhi[8 * 16 * 32 * 2];
__device__ uint g_W2Blo[8 * 16 * 32 * 2];

__device__ __forceinline__ uint packbf(bf16 a, bf16 b) {
    __nv_bfloat162 v = __halves2bfloat162(a, b);
    return *(uint*)&v;
}

__device__ __forceinline__ void mma16816(float4& d, uint a0, uint a1, uint a2, uint a3,
                                         uint b0, uint b1) {
    asm volatile(
        "mma.sync.aligned.m16n8k16.row.col.f32.bf16.bf16.f32 "
        "{%0,%1,%2,%3}, {%4,%5,%6,%7}, {%8,%9}, {%0,%1,%2,%3};"
        : "+f"(d.x), "+f"(d.y), "+f"(d.z), "+f"(d.w)
        : "r"(a0), "r"(a1), "r"(a2), "r"(a3), "r"(b0), "r"(b1));
}

__device__ __forceinline__ void storeSplit(bf16* hi, bf16* lo, int idx, float v) {
    bf16 h = __float2bfloat16_rn(v);
    hi[idx] = h;
    lo[idx] = __float2bfloat16_rn(v - __bfloat162float(h));
}

__global__ void precomp_kernel(const float* __restrict__ W1, const float* __restrict__ a1,
                               const float* __restrict__ W2, const float* __restrict__ a2) {
    int t = threadIdx.x;  // 128 threads
    float s1 = 0.f, s2 = 0.f;
#pragma unroll 8
    for (int j = 0; j < HH; j++) {
        float w = W2[t * HH + j];
        s1 = fmaf(w, a2[j], s1);
        s2 = fmaf(w, a2[HH + j], s2);
    }
    g_c2l[t] = s1;
    g_c2r[t] = s2;
    if (t < INF_) {
        float p = 0.f, q = 0.f;
#pragma unroll 8
        for (int j = 0; j < HH; j++) {
            float w = W1[t * HH + j];
            p = fmaf(w, a1[j], p);
            q = fmaf(w, a1[HH + j], q);
        }
        g_c1l[t] = p;
        g_c1r[t] = q;
    }
    for (int idx = t; idx < 8 * 16 * 32 * 2; idx += 128) {
        int w = idx & 1;
        int lane = (idx >> 1) & 31;
        int nu = (idx >> 6) & 15;
        int ks = idx >> 10;
        int g = lane >> 2, tt = lane & 3;
        int k = ks * 16 + 2 * tt + 8 * w;
        int n = nu * 8 + g;
        float v0 = W2[k * HH + n];
        float v1 = W2[(k + 1) * HH + n];
        bf16 h0 = __float2bfloat16_rn(v0);
        bf16 h1 = __float2bfloat16_rn(v1);
        g_W2Bhi[idx] = packbf(h0, h1);
        g_W2Blo[idx] = packbf(__float2bfloat16_rn(v0 - __bfloat162float(h0)),
                              __float2bfloat16_rn(v1 - __bfloat162float(h1)));
    }
}

__device__ __forceinline__ void softmax64_bf(char* __restrict__ atHi, char* __restrict__ atLo,
                                             const float* __restrict__ sSi,
                                             const float* __restrict__ sSj, int tid) {
    int row = tid >> 3, l8 = tid & 7;
    float si = sSi[row];
    const float* sj = sSj + l8 * 8;
    float ev[8];
    float m = -1e30f;
#pragma unroll
    for (int j = 0; j < 8; j++) {
        float x = si + sj[j];
        x = (x > 0.f) ? x : 0.2f * x;
        ev[j] = x;
        m = fmaxf(m, x);
    }
    m = fmaxf(m, __shfl_xor_sync(0xffffffffu, m, 1));
    m = fmaxf(m, __shfl_xor_sync(0xffffffffu, m, 2));
    m = fmaxf(m, __shfl_xor_sync(0xffffffffu, m, 4));
    float s = 0.f;
#pragma unroll
    for (int j = 0; j < 8; j++) {
        float e = __expf(ev[j] - m);
        ev[j] = e;
        s += e;
    }
    s += __shfl_xor_sync(0xffffffffu, s, 1);
    s += __shfl_xor_sync(0xffffffffu, s, 2);
    s += __shfl_xor_sync(0xffffffffu, s, 4);
    float inv = 1.0f / s;
    uint* dh = (uint*)(atHi + row * (AT_STR * 2) + l8 * 16);
    uint* dl = (uint*)(atLo + row * (AT_STR * 2) + l8 * 16);
#pragma unroll
    for (int p = 0; p < 4; p++) {
        float v0 = ev[2 * p] * inv, v1 = ev[2 * p + 1] * inv;
        bf16 h0 = __float2bfloat16_rn(v0);
        bf16 h1 = __float2bfloat16_rn(v1);
        dh[p] = packbf(h0, h1);
        dl[p] = packbf(__float2bfloat16_rn(v0 - __bfloat162float(h0)),
                       __float2bfloat16_rn(v1 - __bfloat162float(h1)));
    }
}

__device__ __forceinline__ float elu1(float x) {
    return (x > 0.f) ? x : (__expf(x) - 1.0f);
}

__global__ __launch_bounds__(NT, 2) void gat_kernel(
    const float* __restrict__ users, const float* __restrict__ W1,
    const float* __restrict__ W2,
    const float* __restrict__ mw1, const float* __restrict__ mb1,
    const float* __restrict__ mw2, const float* __restrict__ mb2,
    float* __restrict__ out, int B) {
    extern __shared__ char smb[];
    // region0 (34816 B): sH (before P5 stores) and sWt (after) ALIAS each other.
    bf16* sHhi  = (bf16*)(smb);                  // 64 x 136
    bf16* sHlo  = (bf16*)(smb + 17408);
    bf16* sWthi = (bf16*)(smb);                  // 128 x 68 (Wh2 transposed)
    bf16* sWtlo = (bf16*)(smb + 17408);
    char* atHi  = smb + 34816;                   // 64 x 68 bf16
    char* atLo  = smb + 43520;
    float* sF   = (float*)(smb + 52224);
    float* sU    = sF;              // 192
    float* sSi   = sF + 192;        // 64
    float* sSj   = sF + 256;        // 64
    float* sC2l  = sF + 320;        // 128
    float* sC2r  = sF + 448;        // 128
    float* scrA  = sF + 576;        // 512: union { sT(64x4) | sPoolQ(512) }
    float* sT    = scrA;
    float* sPoolQ= scrA;
    float* sPool = sF + 1088;       // 128
    float* sR    = sF + 1216;       // 32
    float* sO    = sF + 1248;       // 128
    float* sSum  = sF + 1376;       // 2

    const int tid  = threadIdx.x;
    const int b    = blockIdx.x;
    const int warp = tid >> 5;
    const int lane = tid & 31;
    const int mi   = warp & 3;           // m16 strip (P7 mapping)
    const int nb   = warp >> 2;          // n32 block (P7 mapping)
    const int g    = lane >> 2;
    const int t4   = lane & 3;

    // ---- P0
    if (tid < MM * INF_) sU[tid] = users[b * (MM * INF_) + tid];
    if (tid < 128) { sC2l[tid] = g_c2l[tid]; sC2r[tid] = g_c2r[tid]; }
    __syncthreads();

    // ---- P1: layer1 si/sj via c1 trick
    if (tid < MM) {
        float u0 = sU[tid * 3], u1 = sU[tid * 3 + 1], u2 = sU[tid * 3 + 2];
        sSi[tid] = u0 * g_c1l[0] + u1 * g_c1l[1] + u2 * g_c1l[2];
        sSj[tid] = u0 * g_c1r[0] + u1 * g_c1r[1] + u2 * g_c1r[2];
    }
    __syncthreads();

    // ---- P2: softmax layer 1 -> attn bf16 hi/lo
    softmax64_bf(atHi, atLo, sSi, sSj, tid);
    __syncthreads();

    // ---- P3a: T = attn1 @ U (rank-3 fusion)
    {
        int row = tid >> 3, l8 = tid & 7;
        const __nv_bfloat162* ah = (const __nv_bfloat162*)(atHi + row * (AT_STR * 2) + l8 * 16);
        const __nv_bfloat162* al = (const __nv_bfloat162*)(atLo + row * (AT_STR * 2) + l8 * 16);
        float t0 = 0.f, t1 = 0.f, t2 = 0.f;
#pragma unroll
        for (int p = 0; p < 4; p++) {
            __nv_bfloat162 h2 = ah[p], l2 = al[p];
            float a0 = __bfloat162float(h2.x) + __bfloat162float(l2.x);
            float a1 = __bfloat162float(h2.y) + __bfloat162float(l2.y);
            const float* u0 = sU + (l8 * 8 + 2 * p) * 3;
            t0 = fmaf(a0, u0[0], t0); t1 = fmaf(a0, u0[1], t1); t2 = fmaf(a0, u0[2], t2);
            t0 = fmaf(a1, u0[3], t0); t1 = fmaf(a1, u0[4], t1); t2 = fmaf(a1, u0[5], t2);
        }
#pragma unroll
        for (int off = 1; off < 8; off <<= 1) {
            t0 += __shfl_xor_sync(0xffffffffu, t0, off);
            t1 += __shfl_xor_sync(0xffffffffu, t1, off);
            t2 += __shfl_xor_sync(0xffffffffu, t2, off);
        }
        if (!l8) {
            sT[row * 4 + 0] = t0;
            sT[row * 4 + 1] = t1;
            sT[row * 4 + 2] = t2;
            sT[row * 4 + 3] = 0.f;
        }
    }
    __syncthreads();

    // ---- P3b: h = elu(T @ W1), thread owns 2 adjacent cols x 8 rows -> packed STS.32
    {
        const int d2 = (tid & 63) * 2;
        const int q8 = tid >> 6;     // 0..7 -> rows q8*8..q8*8+7
        float wa0 = W1[d2],          wb0 = W1[d2 + 1];
        float wa1 = W1[HH + d2],     wb1 = W1[HH + d2 + 1];
        float wa2 = W1[2 * HH + d2], wb2 = W1[2 * HH + d2 + 1];
        uint* rh = (uint*)sHhi;
        uint* rl = (uint*)sHlo;
#pragma unroll
        for (int r = 0; r < 8; r++) {
            int row = q8 * 8 + r;
            float4 tt = *(const float4*)&sT[row * 4];
            float xa = elu1(fmaf(tt.x, wa0, fmaf(tt.y, wa1, tt.z * wa2)));
            float xb = elu1(fmaf(tt.x, wb0, fmaf(tt.y, wb1, tt.z * wb2)));
            bf16 ha = __float2bfloat16_rn(xa);
            bf16 hb = __float2bfloat16_rn(xb);
            rh[row * (SH_STR / 2) + (d2 >> 1)] = packbf(ha, hb);
            rl[row * (SH_STR / 2) + (d2 >> 1)] =
                packbf(__float2bfloat16_rn(xa - __bfloat162float(ha)),
                       __float2bfloat16_rn(xb - __bfloat162float(hb)));
        }
    }
    __syncthreads();

    // ==== P5 (warps 0-7, m32n32 tiles) CONCURRENT WITH P4 (warps 8-15) ====
    float4 acc5[2][4];
    if (warp < 8) {
        const int mi2 = warp & 1;     // m32 strip: rows mi2*32..+31
        const int nb2 = warp >> 1;    // n32 block: cols nb2*32..+31
#pragma unroll
        for (int h = 0; h < 2; h++)
#pragma unroll
            for (int f = 0; f < 4; f++) acc5[h][f] = make_float4(0.f, 0.f, 0.f, 0.f);
#pragma unroll
        for (int ks = 0; ks < 8; ks++) {
            int kb = ks * 16 + 2 * t4;
            uint ah[2][4], al[2][4];
#pragma unroll
            for (int h = 0; h < 2; h++) {
                int arow = mi2 * 32 + h * 16 + g;
                ah[h][0] = *(const uint*)&sHhi[arow * SH_STR + kb];
                ah[h][1] = *(const uint*)&sHhi[(arow + 8) * SH_STR + kb];
                ah[h][2] = *(const uint*)&sHhi[arow * SH_STR + kb + 8];
                ah[h][3] = *(const uint*)&sHhi[(arow + 8) * SH_STR + kb + 8];
                al[h][0] = *(const uint*)&sHlo[arow * SH_STR + kb];
                al[h][1] = *(const uint*)&sHlo[(arow + 8) * SH_STR + kb];
                al[h][2] = *(const uint*)&sHlo[arow * SH_STR + kb + 8];
                al[h][3] = *(const uint*)&sHlo[(arow + 8) * SH_STR + kb + 8];
            }
#pragma unroll
            for (int f = 0; f < 4; f++) {
                int nu = nb2 * 4 + f;
                int bidx = ((ks * 16 + nu) * 32 + lane) * 2;
                uint2 bh = *(const uint2*)&g_W2Bhi[bidx];
                uint2 bl = *(const uint2*)&g_W2Blo[bidx];
#pragma unroll
                for (int h = 0; h < 2; h++) {
                    mma16816(acc5[h][f], ah[h][0], ah[h][1], ah[h][2], ah[h][3], bh.x, bh.y);
                    mma16816(acc5[h][f], ah[h][0], ah[h][1], ah[h][2], ah[h][3], bl.x, bl.y);
                    mma16816(acc5[h][f], al[h][0], al[h][1], al[h][2], al[h][3], bh.x, bh.y);
                }
            }
        }
    } else {
        // ---- P4: layer2 si/sj = h @ c2 on 256 threads (64 rows x 4 lanes of 32 k)
        int t = tid - 256;
        int row = t >> 2, l4 = t & 3;
        const __nv_bfloat162* hh = (const __nv_bfloat162*)(sHhi + row * SH_STR + l4 * 32);
        const __nv_bfloat162* hl = (const __nv_bfloat162*)(sHlo + row * SH_STR + l4 * 32);
        const float* cl = sC2l + l4 * 32;
        const float* cr = sC2r + l4 * 32;
        float s1 = 0.f, s2 = 0.f;
#pragma unroll
        for (int p = 0; p < 16; p++) {
            __nv_bfloat162 h2 = hh[p], l2 = hl[p];
            float h0 = __bfloat162float(h2.x) + __bfloat162float(l2.x);
            float h1 = __bfloat162float(h2.y) + __bfloat162float(l2.y);
            s1 = fmaf(h0, cl[2 * p], s1);     s2 = fmaf(h0, cr[2 * p], s2);
            s1 = fmaf(h1, cl[2 * p + 1], s1); s2 = fmaf(h1, cr[2 * p + 1], s2);
        }
        s1 += __shfl_xor_sync(0xffffffffu, s1, 1);
        s2 += __shfl_xor_sync(0xffffffffu, s2, 1);
        s1 += __shfl_xor_sync(0xffffffffu, s1, 2);
        s2 += __shfl_xor_sync(0xffffffffu, s2, 2);
        if (!l4) { sSi[row] = s1; sSj[row] = s2; }
    }
    __syncthreads();   // P5 reads of sH complete everywhere -> safe to overwrite (sWt aliases sH)

    if (warp < 8) {
        const int mi2 = warp & 1, nb2 = warp >> 1;
#pragma unroll
        for (int h = 0; h < 2; h++) {
            int arow = mi2 * 32 + h * 16 + g;
#pragma unroll
            for (int f = 0; f < 4; f++) {
                int c = nb2 * 32 + f * 8 + 2 * t4;
                storeSplit(sWthi, sWtlo, c * WT_STR + arow,           acc5[h][f].x);
                storeSplit(sWthi, sWtlo, (c + 1) * WT_STR + arow,     acc5[h][f].y);
                storeSplit(sWthi, sWtlo, c * WT_STR + arow + 8,       acc5[h][f].z);
                storeSplit(sWthi, sWtlo, (c + 1) * WT_STR + arow + 8, acc5[h][f].w);
            }
        }
    }
    __syncthreads();

    // ---- P6: softmax layer 2 -> attn bf16 hi/lo
    softmax64_bf(atHi, atLo, sSi, sSj, tid);
    __syncthreads();

    // ---- P7: h2 = elu(attn2 @ Wh2) via bf16x3 MMA (16 warps m16n32), fused max-pool
    {
        const int arow = mi * 16 + g;
        float4 acc[4];
#pragma unroll
        for (int f = 0; f < 4; f++) acc[f] = make_float4(0.f, 0.f, 0.f, 0.f);
#pragma unroll
        for (int ks = 0; ks < 4; ks++) {
            int kb = ks * 16 + 2 * t4;
            uint ah0 = *(const uint*)(atHi + arow * (AT_STR * 2) + kb * 2);
            uint ah1 = *(const uint*)(atHi + (arow + 8) * (AT_STR * 2) + kb * 2);
            uint ah2 = *(const uint*)(atHi + arow * (AT_STR * 2) + kb * 2 + 16);
            uint ah3 = *(const uint*)(atHi + (arow + 8) * (AT_STR * 2) + kb * 2 + 16);
            uint al0 = *(const uint*)(atLo + arow * (AT_STR * 2) + kb * 2);
            uint al1 = *(const uint*)(atLo + (arow + 8) * (AT_STR * 2) + kb * 2);
            uint al2 = *(const uint*)(atLo + arow * (AT_STR * 2) + kb * 2 + 16);
            uint al3 = *(const uint*)(atLo + (arow + 8) * (AT_STR * 2) + kb * 2 + 16);
#pragma unroll
            for (int f = 0; f < 4; f++) {
                int nu = nb * 4 + f;
                uint b0h = *(const uint*)&sWthi[(nu * 8 + g) * WT_STR + kb];
                uint b1h = *(const uint*)&sWthi[(nu * 8 + g) * WT_STR + kb + 8];
                uint b0l = *(const uint*)&sWtlo[(nu * 8 + g) * WT_STR + kb];
                uint b1l = *(const uint*)&sWtlo[(nu * 8 + g) * WT_STR + kb + 8];
                mma16816(acc[f], ah0, ah1, ah2, ah3, b0h, b1h);
                mma16816(acc[f], ah0, ah1, ah2, ah3, b0l, b1l);
                mma16816(acc[f], al0, al1, al2, al3, b0h, b1h);
            }
        }
#pragma unroll
        for (int f = 0; f < 4; f++) {
            float p0 = fmaxf(elu1(acc[f].x), elu1(acc[f].z));
            float p1 = fmaxf(elu1(acc[f].y), elu1(acc[f].w));
#pragma unroll
            for (int off = 4; off < 32; off <<= 1) {
                p0 = fmaxf(p0, __shfl_xor_sync(0xffffffffu, p0, off));
                p1 = fmaxf(p1, __shfl_xor_sync(0xffffffffu, p1, off));
            }
            if (lane < 4) {
                int c = nb * 32 + f * 8 + 2 * lane;
                *(float2*)&sPoolQ[mi * 128 + c] = make_float2(p0, p1);
            }
        }
    }
    __syncthreads();

    // ---- P7b: combine the four m-strips
    if (tid < 128) {
        float p0 = sPoolQ[tid], p1 = sPoolQ[128 + tid];
        float p2 = sPoolQ[256 + tid], p3 = sPoolQ[384 + tid];
        sPool[tid] = fmaxf(fmaxf(p0, p1), fmaxf(p2, p3));
    }
    __syncthreads();

    // ---- P8: hidden = relu(pooled @ mw1 + mb1)
    if (tid < 256) {
        int col = tid >> 3, l8 = tid & 7;
        float acc = 0.f;
        const float* pp = sPool + l8 * 16;
#pragma unroll
        for (int k = 0; k < 16; k++) acc = fmaf(pp[k], mw1[(l8 * 16 + k) * 32 + col], acc);
        acc += __shfl_xor_sync(0xffffffffu, acc, 1);
        acc += __shfl_xor_sync(0xffffffffu, acc, 2);
        acc += __shfl_xor_sync(0xffffffffu, acc, 4);
        if (!l8) sR[col] = fmaxf(acc + mb1[col], 0.f);
    }
    __syncthreads();

    // ---- P9
    if (tid < 128) {
        float acc = mb2[tid];
#pragma unroll
        for (int m = 0; m < 32; m++) acc = fmaf(sR[m], mw2[m * HH + tid], acc);
        sO[tid] = fmaxf(acc, 0.f) + 1e-6f;
    }
    __syncthreads();

    // ---- P10
    if (tid < 2) {
        float s = 0.f;
        const float* p = sO + tid * 64;
#pragma unroll 8
        for (int j = 0; j < 64; j++) s += p[j];
        sSum[tid] = s;
    }
    __syncthreads();

    // ---- P11: normalize & write. power[B,A] then delta[B,A]
    if (tid < 128) {
        const float Bmax = 2.0f * 50.0f - 63.0f * 0.025f;  // 98.425
        const float PMAX = 1.0f;
        if (tid < 64) {
            out[(size_t)B * AA + (size_t)b * AA + tid] = Bmax * sO[tid] / (sSum[0] + 1e-6f);
        } else {
            out[(size_t)b * AA + (tid - 64)] = PMAX * sO[tid] / (sSum[1] + 1e-6f);
        }
    }
}

static const int SMEM_BYTES = 52224 + 1378 * 4;   // 57736

extern "C" void kernel_launch(void* const* d_in, const int* in_sizes, int n_in,
                              void* d_out, int out_size) {
    const float* users = (const float*)d_in[0];
    const float* W1    = (const float*)d_in[1];
    const float* a1    = (const float*)d_in[2];
    const float* W2    = (const float*)d_in[3];
    const float* a2    = (const float*)d_in[4];
    const float* mw1   = (const float*)d_in[5];
    const float* mb1   = (const float*)d_in[6];
    const float* mw2   = (const float*)d_in[7];
    const float* mb2   = (const float*)d_in[8];
    float* out = (float*)d_out;

    int B = in_sizes[0] / (MM * INF_);

    cudaFuncSetAttribute(gat_kernel, cudaFuncAttributeMaxDynamicSharedMemorySize, SMEM_BYTES);

    precomp_kernel<<<1, 128>>>(W1, a1, W2, a2);
    gat_kernel<<<B, NT, SMEM_BYTES>>>(users, W1, W2, mw1, mb1, mw2, mb2, out, B);
}

// round 12
// speedup vs baseline: 1.0839x; 1.0438x over previous
#include <cuda_runtime.h>
#include <cuda_bf16.h>

#define MM   64
#define HH   128
#define INF_ 3
#define AA   64
#define NT   512

#define SH_STR 136   // bf16 units; 272B row stride (== 16 mod 128)
#define AT_STR 72    // bf16 units; 144B row stride (== 16 mod 128)

typedef __nv_bfloat16 bf16;
typedef unsigned int uint;

__device__ float g_c2l[HH], g_c2r[HH], g_c1l[INF_], g_c1r[INF_];
// W2 pre-split (hi/lo bf16), m16n8k16 B-fragment order:
// idx = (((ks*16 + nu)*32 + lane)*2 + w); k = ks*16 + 2*(lane&3) + 8*w, n = nu*8 + (lane>>2)
__device__ uint g_W2Bhi[8 * 16 * 32 * 2];
__device__ uint g_W2Blo[8 * 16 * 32 * 2];

__device__ __forceinline__ uint packbf(bf16 a, bf16 b) {
    __nv_bfloat162 v = __halves2bfloat162(a, b);
    return *(uint*)&v;
}

__device__ __forceinline__ void mma16816(float4& d, uint a0, uint a1, uint a2, uint a3,
                                         uint b0, uint b1) {
    asm volatile(
        "mma.sync.aligned.m16n8k16.row.col.f32.bf16.bf16.f32 "
        "{%0,%1,%2,%3}, {%4,%5,%6,%7}, {%8,%9}, {%0,%1,%2,%3};"
        : "+f"(d.x), "+f"(d.y), "+f"(d.z), "+f"(d.w)
        : "r"(a0), "r"(a1), "r"(a2), "r"(a3), "r"(b0), "r"(b1));
}

__device__ __forceinline__ uint4 ldsm4(uint addr) {
    uint4 r;
    asm volatile("ldmatrix.sync.aligned.m8n8.x4.shared.b16 {%0,%1,%2,%3}, [%4];"
                 : "=r"(r.x), "=r"(r.y), "=r"(r.z), "=r"(r.w) : "r"(addr));
    return r;
}
__device__ __forceinline__ uint4 ldsm4t(uint addr) {
    uint4 r;
    asm volatile("ldmatrix.sync.aligned.m8n8.x4.trans.shared.b16 {%0,%1,%2,%3}, [%4];"
                 : "=r"(r.x), "=r"(r.y), "=r"(r.z), "=r"(r.w) : "r"(addr));
    return r;
}
__device__ __forceinline__ uint smaddr(const void* p) {
    return (uint)__cvta_generic_to_shared(p);
}

__global__ void precomp_kernel(const float* __restrict__ W1, const float* __restrict__ a1,
                               const float* __restrict__ W2, const float* __restrict__ a2) {
    int t = threadIdx.x;  // 128 threads
    float s1 = 0.f, s2 = 0.f;
#pragma unroll 8
    for (int j = 0; j < HH; j++) {
        float w = W2[t * HH + j];
        s1 = fmaf(w, a2[j], s1);
        s2 = fmaf(w, a2[HH + j], s2);
    }
    g_c2l[t] = s1;
    g_c2r[t] = s2;
    if (t < INF_) {
        float p = 0.f, q = 0.f;
#pragma unroll 8
        for (int j = 0; j < HH; j++) {
            float w = W1[t * HH + j];
            p = fmaf(w, a1[j], p);
            q = fmaf(w, a1[HH + j], q);
        }
        g_c1l[t] = p;
        g_c1r[t] = q;
    }
    for (int idx = t; idx < 8 * 16 * 32 * 2; idx += 128) {
        int w = idx & 1;
        int lane = (idx >> 1) & 31;
        int nu = (idx >> 6) & 15;
        int ks = idx >> 10;
        int g = lane >> 2, tt = lane & 3;
        int k = ks * 16 + 2 * tt + 8 * w;
        int n = nu * 8 + g;
        float v0 = W2[k * HH + n];
        float v1 = W2[(k + 1) * HH + n];
        bf16 h0 = __float2bfloat16_rn(v0);
        bf16 h1 = __float2bfloat16_rn(v1);
        g_W2Bhi[idx] = packbf(h0, h1);
        g_W2Blo[idx] = packbf(__float2bfloat16_rn(v0 - __bfloat162float(h0)),
                              __float2bfloat16_rn(v1 - __bfloat162float(h1)));
    }
}

// Softmax over 64 cols, 8 lanes per row; writes bf16 hi/lo attn tiles via STS.128.
__device__ __forceinline__ void softmax64_bf(char* __restrict__ atHi, char* __restrict__ atLo,
                                             const float* __restrict__ sSi,
                                             const float* __restrict__ sSj, int tid) {
    int row = tid >> 3, l8 = tid & 7;
    float si = sSi[row];
    const float* sj = sSj + l8 * 8;
    float ev[8];
    float m = -1e30f;
#pragma unroll
    for (int j = 0; j < 8; j++) {
        float x = si + sj[j];
        x = (x > 0.f) ? x : 0.2f * x;
        ev[j] = x;
        m = fmaxf(m, x);
    }
    m = fmaxf(m, __shfl_xor_sync(0xffffffffu, m, 1));
    m = fmaxf(m, __shfl_xor_sync(0xffffffffu, m, 2));
    m = fmaxf(m, __shfl_xor_sync(0xffffffffu, m, 4));
    float s = 0.f;
#pragma unroll
    for (int j = 0; j < 8; j++) {
        float e = __expf(ev[j] - m);
        ev[j] = e;
        s += e;
    }
    s += __shfl_xor_sync(0xffffffffu, s, 1);
    s += __shfl_xor_sync(0xffffffffu, s, 2);
    s += __shfl_xor_sync(0xffffffffu, s, 4);
    float inv = 1.0f / s;
    uint4 vh, vl;
    uint* ph = &vh.x;
    uint* pl = &vl.x;
#pragma unroll
    for (int p = 0; p < 4; p++) {
        float v0 = ev[2 * p] * inv, v1 = ev[2 * p + 1] * inv;
        bf16 h0 = __float2bfloat16_rn(v0);
        bf16 h1 = __float2bfloat16_rn(v1);
        ph[p] = packbf(h0, h1);
        pl[p] = packbf(__float2bfloat16_rn(v0 - __bfloat162float(h0)),
                       __float2bfloat16_rn(v1 - __bfloat162float(h1)));
    }
    *(uint4*)(atHi + row * (AT_STR * 2) + l8 * 16) = vh;
    *(uint4*)(atLo + row * (AT_STR * 2) + l8 * 16) = vl;
}

__device__ __forceinline__ float elu1(float x) {
    return (x > 0.f) ? x : (__expf(x) - 1.0f);
}

__global__ __launch_bounds__(NT, 2) void gat_kernel(
    const float* __restrict__ users, const float* __restrict__ W1,
    const float* __restrict__ W2,
    const float* __restrict__ mw1, const float* __restrict__ mb1,
    const float* __restrict__ mw2, const float* __restrict__ mb2,
    float* __restrict__ out, int B) {
    extern __shared__ char smb[];
    // region0 (34816 B): sH (before P5 stores) and Wh2 (after, SAME row-major geometry) alias.
    bf16* sHhi  = (bf16*)(smb);                  // 64 x 136
    bf16* sHlo  = (bf16*)(smb + 17408);
    char* atHi  = smb + 34816;                   // 64 x 72 bf16 (144B rows)
    char* atLo  = smb + 44032;
    float* sF   = (float*)(smb + 53248);
    float* sU    = sF;              // 192
    float* sSi   = sF + 192;        // 64
    float* sSj   = sF + 256;        // 64
    float* sC2l  = sF + 320;        // 128
    float* sC2r  = sF + 448;        // 128
    float* scrA  = sF + 576;        // 512: union { sT(64x4) | sPoolQ(512) }
    float* sT    = scrA;
    float* sPoolQ= scrA;
    float* sPool = sF + 1088;       // 128
    float* sR    = sF + 1216;       // 32
    float* sO    = sF + 1248;       // 128
    float* sSum  = sF + 1376;       // 2

    const int tid  = threadIdx.x;
    const int b    = blockIdx.x;
    const int warp = tid >> 5;
    const int lane = tid & 31;
    const int mi   = warp & 3;           // P7: m16 strip
    const int nb   = warp >> 2;          // P7: n32 block
    const int g    = lane >> 2;
    const int t4   = lane & 3;
    // ldmatrix lane decomposition
    const int l7   = lane & 7;
    const int lb8  = (lane >> 3) & 1;
    const int lb16 = lane >> 4;

    // ---- P0
    if (tid < MM * INF_) sU[tid] = users[b * (MM * INF_) + tid];
    if (tid < 128) { sC2l[tid] = g_c2l[tid]; sC2r[tid] = g_c2r[tid]; }
    __syncthreads();

    // ---- P1: layer1 si/sj via c1 trick
    if (tid < MM) {
        float u0 = sU[tid * 3], u1 = sU[tid * 3 + 1], u2 = sU[tid * 3 + 2];
        sSi[tid] = u0 * g_c1l[0] + u1 * g_c1l[1] + u2 * g_c1l[2];
        sSj[tid] = u0 * g_c1r[0] + u1 * g_c1r[1] + u2 * g_c1r[2];
    }
    __syncthreads();

    // ---- P2: softmax layer 1 -> attn bf16 hi/lo
    softmax64_bf(atHi, atLo, sSi, sSj, tid);
    __syncthreads();

    // ---- P3a: T = attn1 @ U (rank-3 fusion), vector LDS.128 reads
    {
        int row = tid >> 3, l8 = tid & 7;
        uint4 h4 = *(const uint4*)(atHi + row * (AT_STR * 2) + l8 * 16);
        uint4 l4v = *(const uint4*)(atLo + row * (AT_STR * 2) + l8 * 16);
        const uint* hp = &h4.x;
        const uint* lp = &l4v.x;
        float t0 = 0.f, t1 = 0.f, t2 = 0.f;
#pragma unroll
        for (int p = 0; p < 4; p++) {
            __nv_bfloat162 h2 = *(const __nv_bfloat162*)&hp[p];
            __nv_bfloat162 l2 = *(const __nv_bfloat162*)&lp[p];
            float a0 = __bfloat162float(h2.x) + __bfloat162float(l2.x);
            float a1 = __bfloat162float(h2.y) + __bfloat162float(l2.y);
            const float* u0 = sU + (l8 * 8 + 2 * p) * 3;
            t0 = fmaf(a0, u0[0], t0); t1 = fmaf(a0, u0[1], t1); t2 = fmaf(a0, u0[2], t2);
            t0 = fmaf(a1, u0[3], t0); t1 = fmaf(a1, u0[4], t1); t2 = fmaf(a1, u0[5], t2);
        }
#pragma unroll
        for (int off = 1; off < 8; off <<= 1) {
            t0 += __shfl_xor_sync(0xffffffffu, t0, off);
            t1 += __shfl_xor_sync(0xffffffffu, t1, off);
            t2 += __shfl_xor_sync(0xffffffffu, t2, off);
        }
        if (!l8) {
            sT[row * 4 + 0] = t0;
            sT[row * 4 + 1] = t1;
            sT[row * 4 + 2] = t2;
            sT[row * 4 + 3] = 0.f;
        }
    }
    __syncthreads();

    // ---- P3b: h = elu(T @ W1), packed STS.32 (2 adjacent cols per thread)
    {
        const int d2 = (tid & 63) * 2;
        const int q8 = tid >> 6;
        float wa0 = W1[d2],          wb0 = W1[d2 + 1];
        float wa1 = W1[HH + d2],     wb1 = W1[HH + d2 + 1];
        float wa2 = W1[2 * HH + d2], wb2 = W1[2 * HH + d2 + 1];
        uint* rh = (uint*)sHhi;
        uint* rl = (uint*)sHlo;
#pragma unroll
        for (int r = 0; r < 8; r++) {
            int row = q8 * 8 + r;
            float4 tt = *(const float4*)&sT[row * 4];
            float xa = elu1(fmaf(tt.x, wa0, fmaf(tt.y, wa1, tt.z * wa2)));
            float xb = elu1(fmaf(tt.x, wb0, fmaf(tt.y, wb1, tt.z * wb2)));
            bf16 ha = __float2bfloat16_rn(xa);
            bf16 hb = __float2bfloat16_rn(xb);
            rh[row * (SH_STR / 2) + (d2 >> 1)] = packbf(ha, hb);
            rl[row * (SH_STR / 2) + (d2 >> 1)] =
                packbf(__float2bfloat16_rn(xa - __bfloat162float(ha)),
                       __float2bfloat16_rn(xb - __bfloat162float(hb)));
        }
    }
    __syncthreads();

    // ==== P5 (warps 0-7, m32n32, LDSM A-frags) CONCURRENT WITH P4 (warps 8-15) ====
    float4 acc5[2][4];
    if (warp < 8) {
        const int mi2 = warp & 1;
        const int nb2 = warp >> 1;
#pragma unroll
        for (int h = 0; h < 2; h++)
#pragma unroll
            for (int f = 0; f < 4; f++) acc5[h][f] = make_float4(0.f, 0.f, 0.f, 0.f);
        // ldmatrix lane address bases (row part constant over ks)
        const int arowl = mi2 * 32 + l7 + lb8 * 8;
        uint aHi0 = smaddr(sHhi) + arowl * (SH_STR * 2) + lb16 * 16;
        uint aLo0 = smaddr(sHlo) + arowl * (SH_STR * 2) + lb16 * 16;
#pragma unroll
        for (int ks = 0; ks < 8; ks++) {
            uint koff = ks * 32;   // 16 bf16 = 32 bytes
            uint4 ah[2], al[2];
#pragma unroll
            for (int h = 0; h < 2; h++) {
                ah[h] = ldsm4(aHi0 + h * (16 * SH_STR * 2) + koff);
                al[h] = ldsm4(aLo0 + h * (16 * SH_STR * 2) + koff);
            }
#pragma unroll
            for (int f = 0; f < 4; f++) {
                int nu = nb2 * 4 + f;
                int bidx = ((ks * 16 + nu) * 32 + lane) * 2;
                uint2 bh = *(const uint2*)&g_W2Bhi[bidx];
                uint2 bl = *(const uint2*)&g_W2Blo[bidx];
#pragma unroll
                for (int h = 0; h < 2; h++) {
                    mma16816(acc5[h][f], ah[h].x, ah[h].y, ah[h].z, ah[h].w, bh.x, bh.y);
                    mma16816(acc5[h][f], ah[h].x, ah[h].y, ah[h].z, ah[h].w, bl.x, bl.y);
                    mma16816(acc5[h][f], al[h].x, al[h].y, al[h].z, al[h].w, bh.x, bh.y);
                }
            }
        }
    } else {
        // ---- P4: layer2 si/sj = h @ c2 on warps 8-15 (64 rows x 4 lanes)
        int t = tid - 256;
        int row = t >> 2, l4 = t & 3;
        const __nv_bfloat162* hh = (const __nv_bfloat162*)(sHhi + row * SH_STR + l4 * 32);
        const __nv_bfloat162* hl = (const __nv_bfloat162*)(sHlo + row * SH_STR + l4 * 32);
        const float* cl = sC2l + l4 * 32;
        const float* cr = sC2r + l4 * 32;
        float s1 = 0.f, s2 = 0.f;
#pragma unroll
        for (int p = 0; p < 16; p++) {
            __nv_bfloat162 h2 = hh[p], l2 = hl[p];
            float h0 = __bfloat162float(h2.x) + __bfloat162float(l2.x);
            float h1 = __bfloat162float(h2.y) + __bfloat162float(l2.y);
            s1 = fmaf(h0, cl[2 * p], s1);     s2 = fmaf(h0, cr[2 * p], s2);
            s1 = fmaf(h1, cl[2 * p + 1], s1); s2 = fmaf(h1, cr[2 * p + 1], s2);
        }
        s1 += __shfl_xor_sync(0xffffffffu, s1, 1);
        s2 += __shfl_xor_sync(0xffffffffu, s2, 1);
        s1 += __shfl_xor_sync(0xffffffffu, s1, 2);
        s2 += __shfl_xor_sync(0xffffffffu, s2, 2);
        if (!l4) { sSi[row] = s1; sSj[row] = s2; }
    }
    __syncthreads();   // all reads of sH done -> safe to overwrite region0 with Wh2

    // P5 stores: Wh2 row-major [node][col], same geometry as sH (packed STS.32)
    if (warp < 8) {
        const int mi2 = warp & 1, nb2 = warp >> 1;
        uint* wh = (uint*)sHhi;
        uint* wl = (uint*)sHlo;
#pragma unroll
        for (int h = 0; h < 2; h++) {
            int r0 = mi2 * 32 + h * 16 + g;
#pragma unroll
            for (int f = 0; f < 4; f++) {
                int cu = (nb2 * 32 + f * 8 + 2 * t4) >> 1;   // uint index of col pair
                float4 v = acc5[h][f];
                bf16 x0 = __float2bfloat16_rn(v.x), y0 = __float2bfloat16_rn(v.y);
                bf16 z0 = __float2bfloat16_rn(v.z), w0 = __float2bfloat16_rn(v.w);
                wh[r0 * (SH_STR / 2) + cu] = packbf(x0, y0);
                wl[r0 * (SH_STR / 2) + cu] =
                    packbf(__float2bfloat16_rn(v.x - __bfloat162float(x0)),
                           __float2bfloat16_rn(v.y - __bfloat162float(y0)));
                wh[(r0 + 8) * (SH_STR / 2) + cu] = packbf(z0, w0);
                wl[(r0 + 8) * (SH_STR / 2) + cu] =
                    packbf(__float2bfloat16_rn(v.z - __bfloat162float(z0)),
                           __float2bfloat16_rn(v.w - __bfloat162float(w0)));
            }
        }
    }
    __syncthreads();

    // ---- P6: softmax layer 2 -> attn bf16 hi/lo
    softmax64_bf(atHi, atLo, sSi, sSj, tid);
    __syncthreads();

    // ---- P7: h2 = elu(attn2 @ Wh2), 16 warps m16n32; A via LDSM, B via LDSM.trans
    {
        float4 acc[4];
#pragma unroll
        for (int f = 0; f < 4; f++) acc[f] = make_float4(0.f, 0.f, 0.f, 0.f);
        const int arowl = mi * 16 + l7 + lb8 * 8;
        uint aHi0 = smaddr(atHi) + arowl * (AT_STR * 2) + lb16 * 16;
        uint aLo0 = smaddr(atLo) + arowl * (AT_STR * 2) + lb16 * 16;
        // B (trans): krow = kb0 + l7 + lb8*8 ; n-chunk = nu*16B, nu = nb*4 + fp*2 + lb16
        const int krl = l7 + lb8 * 8;
        uint bHi0 = smaddr(sHhi) + krl * (SH_STR * 2);
        uint bLo0 = smaddr(sHlo) + krl * (SH_STR * 2);
#pragma unroll
        for (int ks = 0; ks < 4; ks++) {
            uint4 ah = ldsm4(aHi0 + ks * 32);
            uint4 al = ldsm4(aLo0 + ks * 32);
#pragma unroll
            for (int fp = 0; fp < 2; fp++) {
                int nu = nb * 4 + fp * 2 + lb16;
                uint boff = ks * 16 * (SH_STR * 2) + nu * 16;
                uint4 bh = ldsm4t(bHi0 + boff);
                uint4 bl = ldsm4t(bLo0 + boff);
                int f0 = fp * 2, f1 = fp * 2 + 1;
                mma16816(acc[f0], ah.x, ah.y, ah.z, ah.w, bh.x, bh.y);
                mma16816(acc[f0], ah.x, ah.y, ah.z, ah.w, bl.x, bl.y);
                mma16816(acc[f0], al.x, al.y, al.z, al.w, bh.x, bh.y);
                mma16816(acc[f1], ah.x, ah.y, ah.z, ah.w, bh.z, bh.w);
                mma16816(acc[f1], ah.x, ah.y, ah.z, ah.w, bl.z, bl.w);
                mma16816(acc[f1], al.x, al.y, al.z, al.w, bh.z, bh.w);
            }
        }
#pragma unroll
        for (int f = 0; f < 4; f++) {
            float p0 = fmaxf(elu1(acc[f].x), elu1(acc[f].z));
            float p1 = fmaxf(elu1(acc[f].y), elu1(acc[f].w));
#pragma unroll
            for (int off = 4; off < 32; off <<= 1) {
                p0 = fmaxf(p0, __shfl_xor_sync(0xffffffffu, p0, off));
                p1 = fmaxf(p1, __shfl_xor_sync(0xffffffffu, p1, off));
            }
            if (lane < 4) {
                int c = nb * 32 + f * 8 + 2 * lane;
                *(float2*)&sPoolQ[mi * 128 + c] = make_float2(p0, p1);
            }
        }
    }
    __syncthreads();

    // ---- P7b: combine the four m-strips
    if (tid < 128) {
        float p0 = sPoolQ[tid], p1 = sPoolQ[128 + tid];
        float p2 = sPoolQ[256 + tid], p3 = sPoolQ[384 + tid];
        sPool[tid] = fmaxf(fmaxf(p0, p1), fmaxf(p2, p3));
    }
    __syncthreads();

    // ---- P8: hidden = relu(pooled @ mw1 + mb1)
    if (tid < 256) {
        int col = tid >> 3, l8 = tid & 7;
        float acc = 0.f;
        const float* pp = sPool + l8 * 16;
#pragma unroll
        for (int k = 0; k < 16; k++) acc = fmaf(pp[k], mw1[(l8 * 16 + k) * 32 + col], acc);
        acc += __shfl_xor_sync(0xffffffffu, acc, 1);
        acc += __shfl_xor_sync(0xffffffffu, acc, 2);
        acc += __shfl_xor_sync(0xffffffffu, acc, 4);
        if (!l8) sR[col] = fmaxf(acc + mb1[col], 0.f);
    }
    __syncthreads();

    // ---- P9
    if (tid < 128) {
        float acc = mb2[tid];
#pragma unroll
        for (int m = 0; m < 32; m++) acc = fmaf(sR[m], mw2[m * HH + tid], acc);
        sO[tid] = fmaxf(acc, 0.f) + 1e-6f;
    }
    __syncthreads();

    // ---- P10
    if (tid < 2) {
        float s = 0.f;
        const float* p = sO + tid * 64;
#pragma unroll 8
        for (int j = 0; j < 64; j++) s += p[j];
        sSum[tid] = s;
    }
    __syncthreads();

    // ---- P11: normalize & write. power[B,A] then delta[B,A]
    if (tid < 128) {
        const float Bmax = 2.0f * 50.0f - 63.0f * 0.025f;  // 98.425
        const float PMAX = 1.0f;
        if (tid < 64) {
            out[(size_t)B * AA + (size_t)b * AA + tid] = Bmax * sO[tid] / (sSum[0] + 1e-6f);
        } else {
            out[(size_t)b * AA + (tid - 64)] = PMAX * sO[tid] / (sSum[1] + 1e-6f);
        }
    }
}

static const int SMEM_BYTES = 53248 + 1378 * 4;   // 58760

extern "C" void kernel_launch(void* const* d_in, const int* in_sizes, int n_in,
                              void* d_out, int out_size) {
    const float* users = (const float*)d_in[0];
    const float* W1    = (const float*)d_in[1];
    const float* a1    = (const float*)d_in[2];
    const float* W2    = (const float*)d_in[3];
    const float* a2    = (const float*)d_in[4];
    const float* mw1   = (const float*)d_in[5];
    const float* mb1   = (const float*)d_in[6];
    const float* mw2   = (const float*)d_in[7];
    const float* mb2   = (const float*)d_in[8];
    float* out = (float*)d_out;

    int B = in_sizes[0] / (MM * INF_);

    cudaFuncSetAttribute(gat_kernel, cudaFuncAttributeMaxDynamicSharedMemorySize, SMEM_BYTES);

    precomp_kernel<<<1, 128>>>(W1, a1, W2, a2);
    gat_kernel<<<B, NT, SMEM_BYTES>>>(users, W1, W2, mw1, mb1, mw2, mb2, out, B);
}

// round 13
// speedup vs baseline: 1.1086x; 1.0228x over previous
#include <cuda_runtime.h>
#include <cuda_bf16.h>

#define MM   64
#define HH   128
#define INF_ 3
#define AA   64
#define NT   512

#define SH_STR 136   // bf16 units; 272B row stride (== 16 mod 128)
#define AT_STR 72    // bf16 units; 144B row stride (== 16 mod 128)
#define AF_STR 68    // fp32 units; 272B row stride (== 16 mod 128)

typedef __nv_bfloat16 bf16;
typedef unsigned int uint;

__device__ float g_c2l[HH], g_c2r[HH], g_c1l[INF_], g_c1r[INF_];
// W2 hi/lo interleaved, m16n8k16 B-fragment order:
// q = g_W2B[(ks*16+nu)*32 + lane] = {b0hi, b1hi, b0lo, b1lo}
// b{w}: packed {W2[k][n], W2[k+1][n]}, k = ks*16 + 2*(lane&3) + 8*w, n = nu*8 + (lane>>2)
__device__ uint4 g_W2B[8 * 16 * 32];

__device__ __forceinline__ uint pack2(float x, float y) {   // .x=bf16(x), .y=bf16(y)
    uint r;
    asm("cvt.rn.bf16x2.f32 %0, %1, %2;" : "=r"(r) : "f"(y), "f"(x));
    return r;
}
__device__ __forceinline__ float bflo(uint p) { return __uint_as_float(p << 16); }
__device__ __forceinline__ float bfhi(uint p) { return __uint_as_float(p & 0xffff0000u); }
// split two floats into hi-pair / lo-pair bf16x2 words
__device__ __forceinline__ void split2(float x, float y, uint& h, uint& l) {
    h = pack2(x, y);
    l = pack2(x - bflo(h), y - bfhi(h));
}

__device__ __forceinline__ void mma16816(float4& d, uint a0, uint a1, uint a2, uint a3,
                                         uint b0, uint b1) {
    asm volatile(
        "mma.sync.aligned.m16n8k16.row.col.f32.bf16.bf16.f32 "
        "{%0,%1,%2,%3}, {%4,%5,%6,%7}, {%8,%9}, {%0,%1,%2,%3};"
        : "+f"(d.x), "+f"(d.y), "+f"(d.z), "+f"(d.w)
        : "r"(a0), "r"(a1), "r"(a2), "r"(a3), "r"(b0), "r"(b1));
}

__device__ __forceinline__ uint4 ldsm4(uint addr) {
    uint4 r;
    asm volatile("ldmatrix.sync.aligned.m8n8.x4.shared.b16 {%0,%1,%2,%3}, [%4];"
                 : "=r"(r.x), "=r"(r.y), "=r"(r.z), "=r"(r.w) : "r"(addr));
    return r;
}
__device__ __forceinline__ uint4 ldsm4t(uint addr) {
    uint4 r;
    asm volatile("ldmatrix.sync.aligned.m8n8.x4.trans.shared.b16 {%0,%1,%2,%3}, [%4];"
                 : "=r"(r.x), "=r"(r.y), "=r"(r.z), "=r"(r.w) : "r"(addr));
    return r;
}
__device__ __forceinline__ uint smaddr(const void* p) {
    return (uint)__cvta_generic_to_shared(p);
}

__global__ void precomp_kernel(const float* __restrict__ W1, const float* __restrict__ a1,
                               const float* __restrict__ W2, const float* __restrict__ a2) {
    int t = threadIdx.x;  // 128 threads
    float s1 = 0.f, s2 = 0.f;
#pragma unroll 8
    for (int j = 0; j < HH; j++) {
        float w = W2[t * HH + j];
        s1 = fmaf(w, a2[j], s1);
        s2 = fmaf(w, a2[HH + j], s2);
    }
    g_c2l[t] = s1;
    g_c2r[t] = s2;
    if (t < INF_) {
        float p = 0.f, q = 0.f;
#pragma unroll 8
        for (int j = 0; j < HH; j++) {
            float w = W1[t * HH + j];
            p = fmaf(w, a1[j], p);
            q = fmaf(w, a1[HH + j], q);
        }
        g_c1l[t] = p;
        g_c1r[t] = q;
    }
    for (int e = t; e < 8 * 16 * 32; e += 128) {
        int lane = e & 31;
        int nu = (e >> 5) & 15;
        int ks = e >> 9;
        int g = lane >> 2, tt = lane & 3;
        uint4 q;
        uint* qp = &q.x;
#pragma unroll
        for (int w = 0; w < 2; w++) {
            int k = ks * 16 + 2 * tt + 8 * w;
            int n = nu * 8 + g;
            float v0 = W2[k * HH + n];
            float v1 = W2[(k + 1) * HH + n];
            uint h, l;
            split2(v0, v1, h, l);
            qp[w] = h;
            qp[w + 2] = l;
        }
        g_W2B[e] = q;
    }
}

// Layer-1 softmax: fp32 output (no MMA consumer), float4 stores.
__device__ __forceinline__ void softmax64_f32(float* __restrict__ atF,
                                              const float* __restrict__ sSi,
                                              const float* __restrict__ sSj, int tid) {
    int row = tid >> 3, l8 = tid & 7;
    float si = sSi[row];
    const float* sj = sSj + l8 * 8;
    float ev[8];
    float m = -1e30f;
#pragma unroll
    for (int j = 0; j < 8; j++) {
        float x = si + sj[j];
        x = (x > 0.f) ? x : 0.2f * x;
        ev[j] = x;
        m = fmaxf(m, x);
    }
    m = fmaxf(m, __shfl_xor_sync(0xffffffffu, m, 1));
    m = fmaxf(m, __shfl_xor_sync(0xffffffffu, m, 2));
    m = fmaxf(m, __shfl_xor_sync(0xffffffffu, m, 4));
    float s = 0.f;
#pragma unroll
    for (int j = 0; j < 8; j++) {
        float e = __expf(ev[j] - m);
        ev[j] = e;
        s += e;
    }
    s += __shfl_xor_sync(0xffffffffu, s, 1);
    s += __shfl_xor_sync(0xffffffffu, s, 2);
    s += __shfl_xor_sync(0xffffffffu, s, 4);
    float inv = 1.0f / s;
    float* dst = atF + row * AF_STR + l8 * 8;
    *(float4*)dst       = make_float4(ev[0] * inv, ev[1] * inv, ev[2] * inv, ev[3] * inv);
    *(float4*)(dst + 4) = make_float4(ev[4] * inv, ev[5] * inv, ev[6] * inv, ev[7] * inv);
}

// Layer-2 softmax: bf16 hi/lo output for MMA, fused-pack, STS.128.
__device__ __forceinline__ void softmax64_bf(char* __restrict__ atHi, char* __restrict__ atLo,
                                             const float* __restrict__ sSi,
                                             const float* __restrict__ sSj, int tid) {
    int row = tid >> 3, l8 = tid & 7;
    float si = sSi[row];
    const float* sj = sSj + l8 * 8;
    float ev[8];
    float m = -1e30f;
#pragma unroll
    for (int j = 0; j < 8; j++) {
        float x = si + sj[j];
        x = (x > 0.f) ? x : 0.2f * x;
        ev[j] = x;
        m = fmaxf(m, x);
    }
    m = fmaxf(m, __shfl_xor_sync(0xffffffffu, m, 1));
    m = fmaxf(m, __shfl_xor_sync(0xffffffffu, m, 2));
    m = fmaxf(m, __shfl_xor_sync(0xffffffffu, m, 4));
    float s = 0.f;
#pragma unroll
    for (int j = 0; j < 8; j++) {
        float e = __expf(ev[j] - m);
        ev[j] = e;
        s += e;
    }
    s += __shfl_xor_sync(0xffffffffu, s, 1);
    s += __shfl_xor_sync(0xffffffffu, s, 2);
    s += __shfl_xor_sync(0xffffffffu, s, 4);
    float inv = 1.0f / s;
    uint4 vh, vl;
    uint* ph = &vh.x;
    uint* pl = &vl.x;
#pragma unroll
    for (int p = 0; p < 4; p++) {
        split2(ev[2 * p] * inv, ev[2 * p + 1] * inv, ph[p], pl[p]);
    }
    *(uint4*)(atHi + row * (AT_STR * 2) + l8 * 16) = vh;
    *(uint4*)(atLo + row * (AT_STR * 2) + l8 * 16) = vl;
}

__device__ __forceinline__ float elu1(float x) {
    return (x > 0.f) ? x : (__expf(x) - 1.0f);
}

__global__ __launch_bounds__(NT, 2) void gat_kernel(
    const float* __restrict__ users, const float* __restrict__ W1,
    const float* __restrict__ W2,
    const float* __restrict__ mw1, const float* __restrict__ mb1,
    const float* __restrict__ mw2, const float* __restrict__ mb2,
    float* __restrict__ out, int B) {
    extern __shared__ char smb[];
    // region0 (34816 B): sH (before P5 stores) and Wh2 (after, same geometry) alias.
    bf16* sHhi  = (bf16*)(smb);                  // 64 x 136
    bf16* sHlo  = (bf16*)(smb + 17408);
    // region1 (18432 B): union { atF fp32 (layer1, 64x68 f32) | atHi+atLo bf16 (layer2) }
    float* atF  = (float*)(smb + 34816);
    char* atHi  = smb + 34816;                   // 64 x 72 bf16 (144B rows)
    char* atLo  = smb + 44032;
    float* sF   = (float*)(smb + 53248);
    float* sU    = sF;              // 192
    float* sSi   = sF + 192;        // 64
    float* sSj   = sF + 256;        // 64
    float* sC2l  = sF + 320;        // 128
    float* sC2r  = sF + 448;        // 128
    float* scrA  = sF + 576;        // 512: union { sT(64x4) | sPoolQ(512) }
    float* sT    = scrA;
    float* sPoolQ= scrA;
    float* sPool = sF + 1088;       // 128
    float* sR    = sF + 1216;       // 32
    float* sO    = sF + 1248;       // 128
    float* sSum  = sF + 1376;       // 2

    const int tid  = threadIdx.x;
    const int b    = blockIdx.x;
    const int warp = tid >> 5;
    const int lane = tid & 31;
    const int mi   = warp & 3;           // P7: m16 strip
    const int nb   = warp >> 2;          // P7: n32 block
    const int g    = lane >> 2;
    const int t4   = lane & 3;
    const int l7   = lane & 7;
    const int lb8  = (lane >> 3) & 1;
    const int lb16 = lane >> 4;

    // ---- P0
    if (tid < MM * INF_) sU[tid] = users[b * (MM * INF_) + tid];
    if (tid < 128) { sC2l[tid] = g_c2l[tid]; sC2r[tid] = g_c2r[tid]; }
    __syncthreads();

    // ---- P1: layer1 si/sj via c1 trick
    if (tid < MM) {
        float u0 = sU[tid * 3], u1 = sU[tid * 3 + 1], u2 = sU[tid * 3 + 2];
        sSi[tid] = u0 * g_c1l[0] + u1 * g_c1l[1] + u2 * g_c1l[2];
        sSj[tid] = u0 * g_c1r[0] + u1 * g_c1r[1] + u2 * g_c1r[2];
    }
    __syncthreads();

    // ---- P2: softmax layer 1 -> fp32 attn
    softmax64_f32(atF, sSi, sSj, tid);
    __syncthreads();

    // ---- P3a: T = attn1 @ U (rank-3 fusion), fp32 float4 reads
    {
        int row = tid >> 3, l8 = tid & 7;
        const float* ar = atF + row * AF_STR + l8 * 8;
        float4 a0 = *(const float4*)ar;
        float4 a1 = *(const float4*)(ar + 4);
        const float* u = sU + l8 * 24;
        float t0, t1, t2;
        t0 = a0.x * u[0];  t1 = a0.x * u[1];  t2 = a0.x * u[2];
        t0 = fmaf(a0.y, u[3], t0);  t1 = fmaf(a0.y, u[4], t1);  t2 = fmaf(a0.y, u[5], t2);
        t0 = fmaf(a0.z, u[6], t0);  t1 = fmaf(a0.z, u[7], t1);  t2 = fmaf(a0.z, u[8], t2);
        t0 = fmaf(a0.w, u[9], t0);  t1 = fmaf(a0.w, u[10], t1); t2 = fmaf(a0.w, u[11], t2);
        t0 = fmaf(a1.x, u[12], t0); t1 = fmaf(a1.x, u[13], t1); t2 = fmaf(a1.x, u[14], t2);
        t0 = fmaf(a1.y, u[15], t0); t1 = fmaf(a1.y, u[16], t1); t2 = fmaf(a1.y, u[17], t2);
        t0 = fmaf(a1.z, u[18], t0); t1 = fmaf(a1.z, u[19], t1); t2 = fmaf(a1.z, u[20], t2);
        t0 = fmaf(a1.w, u[21], t0); t1 = fmaf(a1.w, u[22], t1); t2 = fmaf(a1.w, u[23], t2);
#pragma unroll
        for (int off = 1; off < 8; off <<= 1) {
            t0 += __shfl_xor_sync(0xffffffffu, t0, off);
            t1 += __shfl_xor_sync(0xffffffffu, t1, off);
            t2 += __shfl_xor_sync(0xffffffffu, t2, off);
        }
        if (!l8) {
            sT[row * 4 + 0] = t0;
            sT[row * 4 + 1] = t1;
            sT[row * 4 + 2] = t2;
            sT[row * 4 + 3] = 0.f;
        }
    }
    __syncthreads();

    // ---- P3b: h = elu(T @ W1), packed STS.32 (2 adjacent cols per thread)
    {
        const int d2 = (tid & 63) * 2;
        const int q8 = tid >> 6;
        float wa0 = W1[d2],          wb0 = W1[d2 + 1];
        float wa1 = W1[HH + d2],     wb1 = W1[HH + d2 + 1];
        float wa2 = W1[2 * HH + d2], wb2 = W1[2 * HH + d2 + 1];
        uint* rh = (uint*)sHhi;
        uint* rl = (uint*)sHlo;
#pragma unroll
        for (int r = 0; r < 8; r++) {
            int row = q8 * 8 + r;
            float4 tt = *(const float4*)&sT[row * 4];
            float xa = elu1(fmaf(tt.x, wa0, fmaf(tt.y, wa1, tt.z * wa2)));
            float xb = elu1(fmaf(tt.x, wb0, fmaf(tt.y, wb1, tt.z * wb2)));
            uint h, l;
            split2(xa, xb, h, l);
            rh[row * (SH_STR / 2) + (d2 >> 1)] = h;
            rl[row * (SH_STR / 2) + (d2 >> 1)] = l;
        }
    }
    __syncthreads();

    // ==== P5 (warps 0-7, m32n32, LDSM A-frags) CONCURRENT WITH P4 (warps 8-15) ====
    float4 acc5[2][4];
    if (warp < 8) {
        const int mi2 = warp & 1;
        const int nb2 = warp >> 1;
#pragma unroll
        for (int h = 0; h < 2; h++)
#pragma unroll
            for (int f = 0; f < 4; f++) acc5[h][f] = make_float4(0.f, 0.f, 0.f, 0.f);
        const int arowl = mi2 * 32 + l7 + lb8 * 8;
        uint aHi0 = smaddr(sHhi) + arowl * (SH_STR * 2) + lb16 * 16;
        uint aLo0 = smaddr(sHlo) + arowl * (SH_STR * 2) + lb16 * 16;
#pragma unroll
        for (int ks = 0; ks < 8; ks++) {
            uint koff = ks * 32;
            uint4 ah[2], al[2];
#pragma unroll
            for (int h = 0; h < 2; h++) {
                ah[h] = ldsm4(aHi0 + h * (16 * SH_STR * 2) + koff);
                al[h] = ldsm4(aLo0 + h * (16 * SH_STR * 2) + koff);
            }
#pragma unroll
            for (int f = 0; f < 4; f++) {
                int nu = nb2 * 4 + f;
                uint4 q = g_W2B[(ks * 16 + nu) * 32 + lane];   // {b0h,b1h,b0l,b1l}
#pragma unroll
                for (int h = 0; h < 2; h++) {
                    mma16816(acc5[h][f], ah[h].x, ah[h].y, ah[h].z, ah[h].w, q.x, q.y);
                    mma16816(acc5[h][f], ah[h].x, ah[h].y, ah[h].z, ah[h].w, q.z, q.w);
                    mma16816(acc5[h][f], al[h].x, al[h].y, al[h].z, al[h].w, q.x, q.y);
                }
            }
        }
    } else {
        // ---- P4: layer2 si/sj = h @ c2 on warps 8-15 (64 rows x 4 lanes)
        int t = tid - 256;
        int row = t >> 2, l4 = t & 3;
        const uint* hh = (const uint*)(sHhi + row * SH_STR + l4 * 32);
        const uint* hl = (const uint*)(sHlo + row * SH_STR + l4 * 32);
        const float* cl = sC2l + l4 * 32;
        const float* cr = sC2r + l4 * 32;
        float s1 = 0.f, s2 = 0.f;
#pragma unroll
        for (int p = 0; p < 16; p++) {
            uint h2 = hh[p], l2 = hl[p];
            float h0 = bflo(h2) + bflo(l2);
            float h1 = bfhi(h2) + bfhi(l2);
            s1 = fmaf(h0, cl[2 * p], s1);     s2 = fmaf(h0, cr[2 * p], s2);
            s1 = fmaf(h1, cl[2 * p + 1], s1); s2 = fmaf(h1, cr[2 * p + 1], s2);
        }
        s1 += __shfl_xor_sync(0xffffffffu, s1, 1);
        s2 += __shfl_xor_sync(0xffffffffu, s2, 1);
        s1 += __shfl_xor_sync(0xffffffffu, s1, 2);
        s2 += __shfl_xor_sync(0xffffffffu, s2, 2);
        if (!l4) { sSi[row] = s1; sSj[row] = s2; }
    }
    __syncthreads();   // all reads of sH done -> safe to overwrite region0 with Wh2

    // P5 stores: Wh2 row-major [node][col], same geometry as sH (packed STS.32)
    if (warp < 8) {
        const int mi2 = warp & 1, nb2 = warp >> 1;
        uint* wh = (uint*)sHhi;
        uint* wl = (uint*)sHlo;
#pragma unroll
        for (int h = 0; h < 2; h++) {
            int r0 = mi2 * 32 + h * 16 + g;
#pragma unroll
            for (int f = 0; f < 4; f++) {
                int cu = (nb2 * 32 + f * 8 + 2 * t4) >> 1;
                float4 v = acc5[h][f];
                uint hw, lw;
                split2(v.x, v.y, hw, lw);
                wh[r0 * (SH_STR / 2) + cu] = hw;
                wl[r0 * (SH_STR / 2) + cu] = lw;
                split2(v.z, v.w, hw, lw);
                wh[(r0 + 8) * (SH_STR / 2) + cu] = hw;
                wl[(r0 + 8) * (SH_STR / 2) + cu] = lw;
            }
        }
    }
    __syncthreads();

    // ---- P6: softmax layer 2 -> attn bf16 hi/lo
    softmax64_bf(atHi, atLo, sSi, sSj, tid);
    __syncthreads();

    // ---- P7: h2 = elu(attn2 @ Wh2), 16 warps m16n32; A via LDSM, B via LDSM.trans
    {
        float4 acc[4];
#pragma unroll
        for (int f = 0; f < 4; f++) acc[f] = make_float4(0.f, 0.f, 0.f, 0.f);
        const int arowl = mi * 16 + l7 + lb8 * 8;
        uint aHi0 = smaddr(atHi) + arowl * (AT_STR * 2) + lb16 * 16;
        uint aLo0 = smaddr(atLo) + arowl * (AT_STR * 2) + lb16 * 16;
        const int krl = l7 + lb8 * 8;
        uint bHi0 = smaddr(sHhi) + krl * (SH_STR * 2);
        uint bLo0 = smaddr(sHlo) + krl * (SH_STR * 2);
#pragma unroll
        for (int ks = 0; ks < 4; ks++) {
            uint4 ah = ldsm4(aHi0 + ks * 32);
            uint4 al = ldsm4(aLo0 + ks * 32);
#pragma unroll
            for (int fp = 0; fp < 2; fp++) {
                int nu = nb * 4 + fp * 2 + lb16;
                uint boff = ks * 16 * (SH_STR * 2) + nu * 16;
                uint4 bh = ldsm4t(bHi0 + boff);
                uint4 bl = ldsm4t(bLo0 + boff);
                int f0 = fp * 2, f1 = fp * 2 + 1;
                mma16816(acc[f0], ah.x, ah.y, ah.z, ah.w, bh.x, bh.y);
                mma16816(acc[f0], ah.x, ah.y, ah.z, ah.w, bl.x, bl.y);
                mma16816(acc[f0], al.x, al.y, al.z, al.w, bh.x, bh.y);
                mma16816(acc[f1], ah.x, ah.y, ah.z, ah.w, bh.z, bh.w);
                mma16816(acc[f1], ah.x, ah.y, ah.z, ah.w, bl.z, bl.w);
                mma16816(acc[f1], al.x, al.y, al.z, al.w, bh.z, bh.w);
            }
        }
#pragma unroll
        for (int f = 0; f < 4; f++) {
            float p0 = fmaxf(elu1(acc[f].x), elu1(acc[f].z));
            float p1 = fmaxf(elu1(acc[f].y), elu1(acc[f].w));
#pragma unroll
            for (int off = 4; off < 32; off <<= 1) {
                p0 = fmaxf(p0, __shfl_xor_sync(0xffffffffu, p0, off));
                p1 = fmaxf(p1, __shfl_xor_sync(0xffffffffu, p1, off));
            }
            if (lane < 4) {
                int c = nb * 32 + f * 8 + 2 * lane;
                *(float2*)&sPoolQ[mi * 128 + c] = make_float2(p0, p1);
            }
        }
    }
    __syncthreads();

    // ---- P7b: combine the four m-strips
    if (tid < 128) {
        float p0 = sPoolQ[tid], p1 = sPoolQ[128 + tid];
        float p2 = sPoolQ[256 + tid], p3 = sPoolQ[384 + tid];
        sPool[tid] = fmaxf(fmaxf(p0, p1), fmaxf(p2, p3));
    }
    __syncthreads();

    // ---- P8: hidden = relu(pooled @ mw1 + mb1)
    if (tid < 256) {
        int col = tid >> 3, l8 = tid & 7;
        float acc = 0.f;
        const float* pp = sPool + l8 * 16;
#pragma unroll
        for (int k = 0; k < 16; k++) acc = fmaf(pp[k], mw1[(l8 * 16 + k) * 32 + col], acc);
        acc += __shfl_xor_sync(0xffffffffu, acc, 1);
        acc += __shfl_xor_sync(0xffffffffu, acc, 2);
        acc += __shfl_xor_sync(0xffffffffu, acc, 4);
        if (!l8) sR[col] = fmaxf(acc + mb1[col], 0.f);
    }
    __syncthreads();

    // ---- P9
    if (tid < 128) {
        float acc = mb2[tid];
#pragma unroll
        for (int m = 0; m < 32; m++) acc = fmaf(sR[m], mw2[m * HH + tid], acc);
        sO[tid] = fmaxf(acc, 0.f) + 1e-6f;
    }
    __syncthreads();

    // ---- P10
    if (tid < 2) {
        float s = 0.f;
        const float* p = sO + tid * 64;
#pragma unroll 8
        for (int j = 0; j < 64; j++) s += p[j];
        sSum[tid] = s;
    }
    __syncthreads();

    // ---- P11: normalize & write. power[B,A] then delta[B,A]
    if (tid < 128) {
        const float Bmax = 2.0f * 50.0f - 63.0f * 0.025f;  // 98.425
        const float PMAX = 1.0f;
        if (tid < 64) {
            out[(size_t)B * AA + (size_t)b * AA + tid] = Bmax * sO[tid] / (sSum[0] + 1e-6f);
        } else {
            out[(size_t)b * AA + (tid - 64)] = PMAX * sO[tid] / (sSum[1] + 1e-6f);
        }
    }
}

static const int SMEM_BYTES = 53248 + 1378 * 4;   // 58760

extern "C" void kernel_launch(void* const* d_in, const int* in_sizes, int n_in,
                              void* d_out, int out_size) {
    const float* users = (const float*)d_in[0];
    const float* W1    = (const float*)d_in[1];
    const float* a1    = (const float*)d_in[2];
    const float* W2    = (const float*)d_in[3];
    const float* a2    = (const float*)d_in[4];
    const float* mw1   = (const float*)d_in[5];
    const float* mb1   = (const float*)d_in[6];
    const float* mw2   = (const float*)d_in[7];
    const float* mb2   = (const float*)d_in[8];
    float* out = (float*)d_out;

    int B = in_sizes[0] / (MM * INF_);

    cudaFuncSetAttribute(gat_kernel, cudaFuncAttributeMaxDynamicSharedMemorySize, SMEM_BYTES);

    precomp_kernel<<<1, 128>>>(W1, a1, W2, a2);
    gat_kernel<<<B, NT, SMEM_BYTES>>>(users, W1, W2, mw1, mb1, mw2, mb2, out, B);
}

// round 14
// speedup vs baseline: 1.2431x; 1.1213x over previous
#include <cuda_runtime.h>
#include <cuda_bf16.h>

#define MM   64
#define HH   128
#define INF_ 3
#define AA   64
#define NT   256

#define SH_STR 136   // bf16 units; 272B row stride (== 16 mod 128)
#define AT_STR 72    // bf16 units; 144B row stride (== 16 mod 128)
#define AF_STR 68    // fp32 units; 272B row stride (== 16 mod 128)

typedef __nv_bfloat16 bf16;
typedef unsigned int uint;

__device__ float g_c2l[HH], g_c2r[HH], g_c1l[INF_], g_c1r[INF_];
// W2 hi/lo interleaved, m16n8k16 B-fragment order:
// q = g_W2B[(ks*16+nu)*32 + lane] = {b0hi, b1hi, b0lo, b1lo}
__device__ uint4 g_W2B[8 * 16 * 32];

__device__ __forceinline__ uint pack2(float x, float y) {
    uint r;
    asm("cvt.rn.bf16x2.f32 %0, %1, %2;" : "=r"(r) : "f"(y), "f"(x));
    return r;
}
__device__ __forceinline__ float bflo(uint p) { return __uint_as_float(p << 16); }
__device__ __forceinline__ float bfhi(uint p) { return __uint_as_float(p & 0xffff0000u); }
__device__ __forceinline__ void split2(float x, float y, uint& h, uint& l) {
    h = pack2(x, y);
    l = pack2(x - bflo(h), y - bfhi(h));
}

__device__ __forceinline__ void mma16816(float4& d, uint a0, uint a1, uint a2, uint a3,
                                         uint b0, uint b1) {
    asm volatile(
        "mma.sync.aligned.m16n8k16.row.col.f32.bf16.bf16.f32 "
        "{%0,%1,%2,%3}, {%4,%5,%6,%7}, {%8,%9}, {%0,%1,%2,%3};"
        : "+f"(d.x), "+f"(d.y), "+f"(d.z), "+f"(d.w)
        : "r"(a0), "r"(a1), "r"(a2), "r"(a3), "r"(b0), "r"(b1));
}

__device__ __forceinline__ uint4 ldsm4(uint addr) {
    uint4 r;
    asm volatile("ldmatrix.sync.aligned.m8n8.x4.shared.b16 {%0,%1,%2,%3}, [%4];"
                 : "=r"(r.x), "=r"(r.y), "=r"(r.z), "=r"(r.w) : "r"(addr));
    return r;
}
__device__ __forceinline__ uint4 ldsm4t(uint addr) {
    uint4 r;
    asm volatile("ldmatrix.sync.aligned.m8n8.x4.trans.shared.b16 {%0,%1,%2,%3}, [%4];"
                 : "=r"(r.x), "=r"(r.y), "=r"(r.z), "=r"(r.w) : "r"(addr));
    return r;
}
__device__ __forceinline__ uint smaddr(const void* p) {
    return (uint)__cvta_generic_to_shared(p);
}

__global__ void precomp_kernel(const float* __restrict__ W1, const float* __restrict__ a1,
                               const float* __restrict__ W2, const float* __restrict__ a2) {
    int t = threadIdx.x;  // 128 threads
    float s1 = 0.f, s2 = 0.f;
#pragma unroll 8
    for (int j = 0; j < HH; j++) {
        float w = W2[t * HH + j];
        s1 = fmaf(w, a2[j], s1);
        s2 = fmaf(w, a2[HH + j], s2);
    }
    g_c2l[t] = s1;
    g_c2r[t] = s2;
    if (t < INF_) {
        float p = 0.f, q = 0.f;
#pragma unroll 8
        for (int j = 0; j < HH; j++) {
            float w = W1[t * HH + j];
            p = fmaf(w, a1[j], p);
            q = fmaf(w, a1[HH + j], q);
        }
        g_c1l[t] = p;
        g_c1r[t] = q;
    }
    for (int e = t; e < 8 * 16 * 32; e += 128) {
        int lane = e & 31;
        int nu = (e >> 5) & 15;
        int ks = e >> 9;
        int g = lane >> 2, tt = lane & 3;
        uint4 q;
        uint* qp = &q.x;
#pragma unroll
        for (int w = 0; w < 2; w++) {
            int k = ks * 16 + 2 * tt + 8 * w;
            int n = nu * 8 + g;
            float v0 = W2[k * HH + n];
            float v1 = W2[(k + 1) * HH + n];
            uint h, l;
            split2(v0, v1, h, l);
            qp[w] = h;
            qp[w + 2] = l;
        }
        g_W2B[e] = q;
    }
}

__device__ __forceinline__ float elu1(float x) {
    return (x > 0.f) ? x : (__expf(x) - 1.0f);
}

// 256-thread softmax core: row = tid>>2, 4 lanes x 16 cols. Returns normalized ev[16].
__device__ __forceinline__ void softmax_core(float* ev, const float* sSi,
                                             const float* sSj, int row, int l4) {
    float si = sSi[row];
    const float* sj = sSj + l4 * 16;
    float m = -1e30f;
#pragma unroll
    for (int j = 0; j < 16; j++) {
        float x = si + sj[j];
        x = (x > 0.f) ? x : 0.2f * x;
        ev[j] = x;
        m = fmaxf(m, x);
    }
    m = fmaxf(m, __shfl_xor_sync(0xffffffffu, m, 1));
    m = fmaxf(m, __shfl_xor_sync(0xffffffffu, m, 2));
    float s = 0.f;
#pragma unroll
    for (int j = 0; j < 16; j++) {
        float e = __expf(ev[j] - m);
        ev[j] = e;
        s += e;
    }
    s += __shfl_xor_sync(0xffffffffu, s, 1);
    s += __shfl_xor_sync(0xffffffffu, s, 2);
    float inv = 1.0f / s;
#pragma unroll
    for (int j = 0; j < 16; j++) ev[j] *= inv;
}

__global__ __launch_bounds__(NT, 4) void gat_kernel(
    const float* __restrict__ users, const float* __restrict__ W1,
    const float* __restrict__ W2,
    const float* __restrict__ mw1, const float* __restrict__ mb1,
    const float* __restrict__ mw2, const float* __restrict__ mb2,
    float* __restrict__ out, int B) {
    extern __shared__ char smb[];
    // region0 (34816 B): sH (before P5 stores) and Wh2 (after, same geometry) alias.
    bf16* sHhi  = (bf16*)(smb);                  // 64 x 136
    bf16* sHlo  = (bf16*)(smb + 17408);
    // region1 (18432 B): union { atF fp32 (layer1) | atHi+atLo bf16 (layer2) }
    float* atF  = (float*)(smb + 34816);
    char* atHi  = smb + 34816;                   // 64 x 72 bf16 (144B rows)
    char* atLo  = smb + 44032;
    float* sF   = (float*)(smb + 53248);
    float* sU    = sF;              // 192
    float* sSi   = sF + 192;        // 64
    float* sSj   = sF + 256;        // 64
    float* sC2l  = sF + 320;        // 128
    float* sC2r  = sF + 448;        // 128
    float* scrA  = sF + 576;        // 256: union { sT(64x4) | sPoolQ(2x128) }
    float* sT    = scrA;
    float* sPoolQ= scrA;
    float* sPool = sF + 832;        // 128
    float* sR    = sF + 960;        // 32
    float* sO    = sF + 992;        // 128
    float* sSum  = sF + 1120;       // 2

    const int tid  = threadIdx.x;
    const int b    = blockIdx.x;
    const int warp = tid >> 5;           // 0..7
    const int lane = tid & 31;
    const int mi2  = warp & 1;           // m32 strip
    const int nb2  = warp >> 1;          // n32 block (0..3)
    const int g    = lane >> 2;
    const int t4   = lane & 3;
    const int l7   = lane & 7;
    const int lb8  = (lane >> 3) & 1;
    const int lb16 = lane >> 4;
    const int row4 = tid >> 2;           // 0..63
    const int l4   = tid & 3;

    // ---- P0
    if (tid < MM * INF_) sU[tid] = users[b * (MM * INF_) + tid];
    if (tid < 128) { sC2l[tid] = g_c2l[tid]; sC2r[tid] = g_c2r[tid]; }
    __syncthreads();

    // ---- P1: layer1 si/sj via c1 trick
    if (tid < MM) {
        float u0 = sU[tid * 3], u1 = sU[tid * 3 + 1], u2 = sU[tid * 3 + 2];
        sSi[tid] = u0 * g_c1l[0] + u1 * g_c1l[1] + u2 * g_c1l[2];
        sSj[tid] = u0 * g_c1r[0] + u1 * g_c1r[1] + u2 * g_c1r[2];
    }
    __syncthreads();

    // ---- P2: softmax layer 1 -> fp32 attn (64 rows x 4 lanes x 16 cols)
    {
        float ev[16];
        softmax_core(ev, sSi, sSj, row4, l4);
        float* dst = atF + row4 * AF_STR + l4 * 16;
#pragma unroll
        for (int p = 0; p < 4; p++)
            *(float4*)(dst + 4 * p) = make_float4(ev[4 * p], ev[4 * p + 1],
                                                  ev[4 * p + 2], ev[4 * p + 3]);
    }
    __syncthreads();

    // ---- P3a: T = attn1 @ U (rank-3 fusion)
    {
        const float* ar = atF + row4 * AF_STR + l4 * 16;
        float av[16];
#pragma unroll
        for (int p = 0; p < 4; p++) *(float4*)&av[4 * p] = *(const float4*)(ar + 4 * p);
        const float* u = sU + l4 * 48;
        float t0 = 0.f, t1 = 0.f, t2 = 0.f;
#pragma unroll
        for (int j = 0; j < 16; j++) {
            float a = av[j];
            t0 = fmaf(a, u[3 * j], t0);
            t1 = fmaf(a, u[3 * j + 1], t1);
            t2 = fmaf(a, u[3 * j + 2], t2);
        }
        t0 += __shfl_xor_sync(0xffffffffu, t0, 1);
        t1 += __shfl_xor_sync(0xffffffffu, t1, 1);
        t2 += __shfl_xor_sync(0xffffffffu, t2, 1);
        t0 += __shfl_xor_sync(0xffffffffu, t0, 2);
        t1 += __shfl_xor_sync(0xffffffffu, t1, 2);
        t2 += __shfl_xor_sync(0xffffffffu, t2, 2);
        if (!l4) {
            sT[row4 * 4 + 0] = t0;
            sT[row4 * 4 + 1] = t1;
            sT[row4 * 4 + 2] = t2;
            sT[row4 * 4 + 3] = 0.f;
        }
    }
    __syncthreads();

    // ---- P3b: h = elu(T @ W1), 2 adjacent cols x 16 rows per thread, packed STS.32
    {
        const int d2 = (tid & 63) * 2;
        const int q16 = tid >> 6;    // 0..3 -> rows q16*16..+15
        float wa0 = W1[d2],          wb0 = W1[d2 + 1];
        float wa1 = W1[HH + d2],     wb1 = W1[HH + d2 + 1];
        float wa2 = W1[2 * HH + d2], wb2 = W1[2 * HH + d2 + 1];
        uint* rh = (uint*)sHhi;
        uint* rl = (uint*)sHlo;
#pragma unroll
        for (int r = 0; r < 16; r++) {
            int row = q16 * 16 + r;
            float4 tt = *(const float4*)&sT[row * 4];
            float xa = elu1(fmaf(tt.x, wa0, fmaf(tt.y, wa1, tt.z * wa2)));
            float xb = elu1(fmaf(tt.x, wb0, fmaf(tt.y, wb1, tt.z * wb2)));
            uint h, l;
            split2(xa, xb, h, l);
            rh[row * (SH_STR / 2) + (d2 >> 1)] = h;
            rl[row * (SH_STR / 2) + (d2 >> 1)] = l;
        }
    }
    __syncthreads();

    // ---- P4: layer2 si/sj = h @ c2 (64 rows x 4 lanes); no barrier needed before P5
    {
        const uint* hh = (const uint*)(sHhi + row4 * SH_STR + l4 * 32);
        const uint* hl = (const uint*)(sHlo + row4 * SH_STR + l4 * 32);
        const float* cl = sC2l + l4 * 32;
        const float* cr = sC2r + l4 * 32;
        float s1 = 0.f, s2 = 0.f;
#pragma unroll
        for (int p = 0; p < 16; p++) {
            uint h2 = hh[p], l2 = hl[p];
            float h0 = bflo(h2) + bflo(l2);
            float h1 = bfhi(h2) + bfhi(l2);
            s1 = fmaf(h0, cl[2 * p], s1);     s2 = fmaf(h0, cr[2 * p], s2);
            s1 = fmaf(h1, cl[2 * p + 1], s1); s2 = fmaf(h1, cr[2 * p + 1], s2);
        }
        s1 += __shfl_xor_sync(0xffffffffu, s1, 1);
        s2 += __shfl_xor_sync(0xffffffffu, s2, 1);
        s1 += __shfl_xor_sync(0xffffffffu, s1, 2);
        s2 += __shfl_xor_sync(0xffffffffu, s2, 2);
        if (!l4) { sSi[row4] = s1; sSj[row4] = s2; }
    }

    // ---- P5: Wh2 = h @ W2, 8 warps m32n32, LDSM A-frags
    {
        float4 acc5[2][4];
#pragma unroll
        for (int h = 0; h < 2; h++)
#pragma unroll
            for (int f = 0; f < 4; f++) acc5[h][f] = make_float4(0.f, 0.f, 0.f, 0.f);
        const int arowl = mi2 * 32 + l7 + lb8 * 8;
        uint aHi0 = smaddr(sHhi) + arowl * (SH_STR * 2) + lb16 * 16;
        uint aLo0 = smaddr(sHlo) + arowl * (SH_STR * 2) + lb16 * 16;
#pragma unroll
        for (int ks = 0; ks < 8; ks++) {
            uint koff = ks * 32;
            uint4 ah[2], al[2];
#pragma unroll
            for (int h = 0; h < 2; h++) {
                ah[h] = ldsm4(aHi0 + h * (16 * SH_STR * 2) + koff);
                al[h] = ldsm4(aLo0 + h * (16 * SH_STR * 2) + koff);
            }
#pragma unroll
            for (int f = 0; f < 4; f++) {
                int nu = nb2 * 4 + f;
                uint4 q = g_W2B[(ks * 16 + nu) * 32 + lane];
#pragma unroll
                for (int h = 0; h < 2; h++) {
                    mma16816(acc5[h][f], ah[h].x, ah[h].y, ah[h].z, ah[h].w, q.x, q.y);
                    mma16816(acc5[h][f], ah[h].x, ah[h].y, ah[h].z, ah[h].w, q.z, q.w);
                    mma16816(acc5[h][f], al[h].x, al[h].y, al[h].z, al[h].w, q.x, q.y);
                }
            }
        }
        __syncthreads();   // all reads of sH done -> safe to overwrite region0 with Wh2
        uint* wh = (uint*)sHhi;
        uint* wl = (uint*)sHlo;
#pragma unroll
        for (int h = 0; h < 2; h++) {
            int r0 = mi2 * 32 + h * 16 + g;
#pragma unroll
            for (int f = 0; f < 4; f++) {
                int cu = (nb2 * 32 + f * 8 + 2 * t4) >> 1;
                float4 v = acc5[h][f];
                uint hw, lw;
                split2(v.x, v.y, hw, lw);
                wh[r0 * (SH_STR / 2) + cu] = hw;
                wl[r0 * (SH_STR / 2) + cu] = lw;
                split2(v.z, v.w, hw, lw);
                wh[(r0 + 8) * (SH_STR / 2) + cu] = hw;
                wl[(r0 + 8) * (SH_STR / 2) + cu] = lw;
            }
        }
    }
    __syncthreads();

    // ---- P6: softmax layer 2 -> attn bf16 hi/lo
    {
        float ev[16];
        softmax_core(ev, sSi, sSj, row4, l4);
        uint4 vh, vl;
        uint* ph = &vh.x;
        uint* pl = &vl.x;
#pragma unroll
        for (int p = 0; p < 4; p++) split2(ev[2 * p], ev[2 * p + 1], ph[p], pl[p]);
        *(uint4*)(atHi + row4 * (AT_STR * 2) + l4 * 32) = vh;
        *(uint4*)(atLo + row4 * (AT_STR * 2) + l4 * 32) = vl;
#pragma unroll
        for (int p = 0; p < 4; p++) split2(ev[8 + 2 * p], ev[9 + 2 * p], ph[p], pl[p]);
        *(uint4*)(atHi + row4 * (AT_STR * 2) + l4 * 32 + 16) = vh;
        *(uint4*)(atLo + row4 * (AT_STR * 2) + l4 * 32 + 16) = vl;
    }
    __syncthreads();

    // ---- P7: h2 = elu(attn2 @ Wh2), 8 warps m32n32; A via LDSM, B via LDSM.trans
    {
        float4 acc[2][4];
#pragma unroll
        for (int h = 0; h < 2; h++)
#pragma unroll
            for (int f = 0; f < 4; f++) acc[h][f] = make_float4(0.f, 0.f, 0.f, 0.f);
        const int arowl = mi2 * 32 + l7 + lb8 * 8;
        uint aHi0 = smaddr(atHi) + arowl * (AT_STR * 2) + lb16 * 16;
        uint aLo0 = smaddr(atLo) + arowl * (AT_STR * 2) + lb16 * 16;
        const int krl = l7 + lb8 * 8;
        uint bHi0 = smaddr(sHhi) + krl * (SH_STR * 2);
        uint bLo0 = smaddr(sHlo) + krl * (SH_STR * 2);
#pragma unroll
        for (int ks = 0; ks < 4; ks++) {
            uint4 ah[2], al[2];
#pragma unroll
            for (int h = 0; h < 2; h++) {
                ah[h] = ldsm4(aHi0 + h * (16 * AT_STR * 2) + ks * 32);
                al[h] = ldsm4(aLo0 + h * (16 * AT_STR * 2) + ks * 32);
            }
#pragma unroll
            for (int fp = 0; fp < 2; fp++) {
                int nu = nb2 * 4 + fp * 2 + lb16;
                uint boff = ks * 16 * (SH_STR * 2) + nu * 16;
                uint4 bh = ldsm4t(bHi0 + boff);
                uint4 bl = ldsm4t(bLo0 + boff);
                int f0 = fp * 2, f1 = fp * 2 + 1;
#pragma unroll
                for (int h = 0; h < 2; h++) {
                    mma16816(acc[h][f0], ah[h].x, ah[h].y, ah[h].z, ah[h].w, bh.x, bh.y);
                    mma16816(acc[h][f0], ah[h].x, ah[h].y, ah[h].z, ah[h].w, bl.x, bl.y);
                    mma16816(acc[h][f0], al[h].x, al[h].y, al[h].z, al[h].w, bh.x, bh.y);
                    mma16816(acc[h][f1], ah[h].x, ah[h].y, ah[h].z, ah[h].w, bh.z, bh.w);
                    mma16816(acc[h][f1], ah[h].x, ah[h].y, ah[h].z, ah[h].w, bl.z, bl.w);
                    mma16816(acc[h][f1], al[h].x, al[h].y, al[h].z, al[h].w, bh.z, bh.w);
                }
            }
        }
#pragma unroll
        for (int f = 0; f < 4; f++) {
            float p0 = -1e30f, p1 = -1e30f;
#pragma unroll
            for (int h = 0; h < 2; h++) {
                p0 = fmaxf(p0, fmaxf(elu1(acc[h][f].x), elu1(acc[h][f].z)));
                p1 = fmaxf(p1, fmaxf(elu1(acc[h][f].y), elu1(acc[h][f].w)));
            }
#pragma unroll
            for (int off = 4; off < 32; off <<= 1) {
                p0 = fmaxf(p0, __shfl_xor_sync(0xffffffffu, p0, off));
                p1 = fmaxf(p1, __shfl_xor_sync(0xffffffffu, p1, off));
            }
            if (lane < 4) {
                int c = nb2 * 32 + f * 8 + 2 * lane;
                *(float2*)&sPoolQ[mi2 * 128 + c] = make_float2(p0, p1);
            }
        }
    }
    __syncthreads();

    // ---- P7b: combine the two m-strips
    if (tid < 128) sPool[tid] = fmaxf(sPoolQ[tid], sPoolQ[128 + tid]);
    __syncthreads();

    // ---- P8: hidden = relu(pooled @ mw1 + mb1)  (32 cols x 8 lanes)
    {
        int col = tid >> 3, l8 = tid & 7;
        float acc = 0.f;
        const float* pp = sPool + l8 * 16;
#pragma unroll
        for (int k = 0; k < 16; k++) acc = fmaf(pp[k], mw1[(l8 * 16 + k) * 32 + col], acc);
        acc += __shfl_xor_sync(0xffffffffu, acc, 1);
        acc += __shfl_xor_sync(0xffffffffu, acc, 2);
        acc += __shfl_xor_sync(0xffffffffu, acc, 4);
        if (!l8) sR[col] = fmaxf(acc + mb1[col], 0.f);
    }
    __syncthreads();

    // ---- P9
    if (tid < 128) {
        float acc = mb2[tid];
#pragma unroll
        for (int m = 0; m < 32; m++) acc = fmaf(sR[m], mw2[m * HH + tid], acc);
        sO[tid] = fmaxf(acc, 0.f) + 1e-6f;
    }
    __syncthreads();

    // ---- P10
    if (tid < 2) {
        float s = 0.f;
        const float* p = sO + tid * 64;
#pragma unroll 8
        for (int j = 0; j < 64; j++) s += p[j];
        sSum[tid] = s;
    }
    __syncthreads();

    // ---- P11: normalize & write. power[B,A] then delta[B,A]
    if (tid < 128) {
        const float Bmax = 2.0f * 50.0f - 63.0f * 0.025f;  // 98.425
        const float PMAX = 1.0f;
        if (tid < 64) {
            out[(size_t)B * AA + (size_t)b * AA + tid] = Bmax * sO[tid] / (sSum[0] + 1e-6f);
        } else {
            out[(size_t)b * AA + (tid - 64)] = PMAX * sO[tid] / (sSum[1] + 1e-6f);
        }
    }
}

static const int SMEM_BYTES = 53248 + 1122 * 4;   // 57736

extern "C" void kernel_launch(void* const* d_in, const int* in_sizes, int n_in,
                              void* d_out, int out_size) {
    const float* users = (const float*)d_in[0];
    const float* W1    = (const float*)d_in[1];
    const float* a1    = (const float*)d_in[2];
    const float* W2    = (const float*)d_in[3];
    const float* a2    = (const float*)d_in[4];
    const float* mw1   = (const float*)d_in[5];
    const float* mb1   = (const float*)d_in[6];
    const float* mw2   = (const float*)d_in[7];
    const float* mb2   = (const float*)d_in[8];
    float* out = (float*)d_out;

    int B = in_sizes[0] / (MM * INF_);

    cudaFuncSetAttribute(gat_kernel, cudaFuncAttributeMaxDynamicSharedMemorySize, SMEM_BYTES);

    precomp_kernel<<<1, 128>>>(W1, a1, W2, a2);
    gat_kernel<<<B, NT, SMEM_BYTES>>>(users, W1, W2, mw1, mb1, mw2, mb2, out, B);
}

// round 15
// speedup vs baseline: 1.2999x; 1.0457x over previous
#include <cuda_runtime.h>
#include <cuda_bf16.h>

#define MM   64
#define HH   128
#define INF_ 3
#define AA   64
#define NT   256

#define SH_STR 136   // bf16 units; 272B row stride (== 16 mod 128)
#define AT_STR 72    // bf16 units; 144B row stride (== 16 mod 128)
#define AF_STR 68    // fp32 units; 272B row stride (== 16 mod 128)

typedef __nv_bfloat16 bf16;
typedef unsigned int uint;

__device__ float g_c2l[HH], g_c2r[HH], g_c1l[INF_], g_c1r[INF_];
// W2 hi/lo interleaved, m16n8k16 B-fragment order:
// q = g_W2B[(ks*16+nu)*32 + lane] = {b0hi, b1hi, b0lo, b1lo}
__device__ uint4 g_W2B[8 * 16 * 32];

__device__ __forceinline__ uint pack2(float x, float y) {
    uint r;
    asm("cvt.rn.bf16x2.f32 %0, %1, %2;" : "=r"(r) : "f"(y), "f"(x));
    return r;
}
__device__ __forceinline__ float bflo(uint p) { return __uint_as_float(p << 16); }
__device__ __forceinline__ float bfhi(uint p) { return __uint_as_float(p & 0xffff0000u); }
__device__ __forceinline__ void split2(float x, float y, uint& h, uint& l) {
    h = pack2(x, y);
    l = pack2(x - bflo(h), y - bfhi(h));
}

__device__ __forceinline__ void mma16816(float4& d, uint a0, uint a1, uint a2, uint a3,
                                         uint b0, uint b1) {
    asm volatile(
        "mma.sync.aligned.m16n8k16.row.col.f32.bf16.bf16.f32 "
        "{%0,%1,%2,%3}, {%4,%5,%6,%7}, {%8,%9}, {%0,%1,%2,%3};"
        : "+f"(d.x), "+f"(d.y), "+f"(d.z), "+f"(d.w)
        : "r"(a0), "r"(a1), "r"(a2), "r"(a3), "r"(b0), "r"(b1));
}

__device__ __forceinline__ uint4 ldsm4(uint addr) {
    uint4 r;
    asm volatile("ldmatrix.sync.aligned.m8n8.x4.shared.b16 {%0,%1,%2,%3}, [%4];"
                 : "=r"(r.x), "=r"(r.y), "=r"(r.z), "=r"(r.w) : "r"(addr));
    return r;
}
__device__ __forceinline__ uint4 ldsm4t(uint addr) {
    uint4 r;
    asm volatile("ldmatrix.sync.aligned.m8n8.x4.trans.shared.b16 {%0,%1,%2,%3}, [%4];"
                 : "=r"(r.x), "=r"(r.y), "=r"(r.z), "=r"(r.w) : "r"(addr));
    return r;
}
__device__ __forceinline__ uint smaddr(const void* p) {
    return (uint)__cvta_generic_to_shared(p);
}

__global__ void precomp_kernel(const float* __restrict__ W1, const float* __restrict__ a1,
                               const float* __restrict__ W2, const float* __restrict__ a2) {
    int t = threadIdx.x;  // 128 threads
    float s1 = 0.f, s2 = 0.f;
#pragma unroll 8
    for (int j = 0; j < HH; j++) {
        float w = W2[t * HH + j];
        s1 = fmaf(w, a2[j], s1);
        s2 = fmaf(w, a2[HH + j], s2);
    }
    g_c2l[t] = s1;
    g_c2r[t] = s2;
    if (t < INF_) {
        float p = 0.f, q = 0.f;
#pragma unroll 8
        for (int j = 0; j < HH; j++) {
            float w = W1[t * HH + j];
            p = fmaf(w, a1[j], p);
            q = fmaf(w, a1[HH + j], q);
        }
        g_c1l[t] = p;
        g_c1r[t] = q;
    }
    for (int e = t; e < 8 * 16 * 32; e += 128) {
        int lane = e & 31;
        int nu = (e >> 5) & 15;
        int ks = e >> 9;
        int g = lane >> 2, tt = lane & 3;
        uint4 q;
        uint* qp = &q.x;
#pragma unroll
        for (int w = 0; w < 2; w++) {
            int k = ks * 16 + 2 * tt + 8 * w;
            int n = nu * 8 + g;
            float v0 = W2[k * HH + n];
            float v1 = W2[(k + 1) * HH + n];
            uint h, l;
            split2(v0, v1, h, l);
            qp[w] = h;
            qp[w + 2] = l;
        }
        g_W2B[e] = q;
    }
}

__device__ __forceinline__ float elu1(float x) {
    return (x > 0.f) ? x : (__expf(x) - 1.0f);
}

// 256-thread softmax core: row = tid>>2, 4 lanes x 16 cols. Returns normalized ev[16].
__device__ __forceinline__ void softmax_core(float* ev, const float* sSi,
                                             const float* sSj, int row, int l4) {
    float si = sSi[row];
    const float* sj = sSj + l4 * 16;
    float m = -1e30f;
#pragma unroll
    for (int j = 0; j < 16; j++) {
        float x = si + sj[j];
        x = (x > 0.f) ? x : 0.2f * x;
        ev[j] = x;
        m = fmaxf(m, x);
    }
    m = fmaxf(m, __shfl_xor_sync(0xffffffffu, m, 1));
    m = fmaxf(m, __shfl_xor_sync(0xffffffffu, m, 2));
    float s = 0.f;
#pragma unroll
    for (int j = 0; j < 16; j++) {
        float e = __expf(ev[j] - m);
        ev[j] = e;
        s += e;
    }
    s += __shfl_xor_sync(0xffffffffu, s, 1);
    s += __shfl_xor_sync(0xffffffffu, s, 2);
    float inv = 1.0f / s;
#pragma unroll
    for (int j = 0; j < 16; j++) ev[j] *= inv;
}

__global__ __launch_bounds__(NT, 4) void gat_kernel(
    const float* __restrict__ users, const float* __restrict__ W1,
    const float* __restrict__ W2,
    const float* __restrict__ mw1, const float* __restrict__ mb1,
    const float* __restrict__ mw2, const float* __restrict__ mb2,
    float* __restrict__ out, int B) {
    extern __shared__ char smb[];
    // region0 (34816 B): sH (before P5 stores) and Wh2 (after, same geometry) alias.
    bf16* sHhi  = (bf16*)(smb);                  // 64 x 136
    bf16* sHlo  = (bf16*)(smb + 17408);
    // region1 (18432 B): union { atF fp32 (layer1) | atHi+atLo bf16 (layer2) }
    float* atF  = (float*)(smb + 34816);
    char* atHi  = smb + 34816;                   // 64 x 72 bf16 (144B rows)
    char* atLo  = smb + 44032;
    float* sF   = (float*)(smb + 53248);
    float* sU    = sF;              // 192 (dead after P3a)
    float* sPool = sF;              // 128, ALIASES sU (written P7b, read P8)
    float* sSi   = sF + 192;        // 64
    float* sSj   = sF + 256;        // 64
    float* sC2l  = sF + 320;        // 128
    float* sC2r  = sF + 448;        // 128
    float* scrA  = sF + 576;        // 256: union { sT(64x4) | sPoolQ(2x128) }
    float* sT    = scrA;
    float* sPoolQ= scrA;
    float* sR    = sF + 832;        // 32
    float* sO    = sF + 864;        // 128
    float* sSum  = sF + 992;        // 2

    const int tid  = threadIdx.x;
    const int b    = blockIdx.x;
    const int warp = tid >> 5;           // 0..7
    const int lane = tid & 31;
    const int mi2  = warp & 1;           // m32 strip
    const int nb2  = warp >> 1;          // n32 block (0..3)
    const int g    = lane >> 2;
    const int t4   = lane & 3;
    const int l7   = lane & 7;
    const int lb8  = (lane >> 3) & 1;
    const int lb16 = lane >> 4;
    const int row4 = tid >> 2;           // 0..63
    const int l4   = tid & 3;

    // ---- P0
    if (tid < MM * INF_) sU[tid] = users[b * (MM * INF_) + tid];
    if (tid < 128) { sC2l[tid] = g_c2l[tid]; sC2r[tid] = g_c2r[tid]; }
    __syncthreads();

    // ---- P1: layer1 si/sj via c1 trick
    if (tid < MM) {
        float u0 = sU[tid * 3], u1 = sU[tid * 3 + 1], u2 = sU[tid * 3 + 2];
        sSi[tid] = u0 * g_c1l[0] + u1 * g_c1l[1] + u2 * g_c1l[2];
        sSj[tid] = u0 * g_c1r[0] + u1 * g_c1r[1] + u2 * g_c1r[2];
    }
    __syncthreads();

    // ---- P2: softmax layer 1 -> fp32 attn (64 rows x 4 lanes x 16 cols)
    {
        float ev[16];
        softmax_core(ev, sSi, sSj, row4, l4);
        float* dst = atF + row4 * AF_STR + l4 * 16;
#pragma unroll
        for (int p = 0; p < 4; p++)
            *(float4*)(dst + 4 * p) = make_float4(ev[4 * p], ev[4 * p + 1],
                                                  ev[4 * p + 2], ev[4 * p + 3]);
    }
    __syncthreads();

    // ---- P3a: T = attn1 @ U (rank-3 fusion)
    {
        const float* ar = atF + row4 * AF_STR + l4 * 16;
        float av[16];
#pragma unroll
        for (int p = 0; p < 4; p++) *(float4*)&av[4 * p] = *(const float4*)(ar + 4 * p);
        const float* u = sU + l4 * 48;
        float t0 = 0.f, t1 = 0.f, t2 = 0.f;
#pragma unroll
        for (int j = 0; j < 16; j++) {
            float a = av[j];
            t0 = fmaf(a, u[3 * j], t0);
            t1 = fmaf(a, u[3 * j + 1], t1);
            t2 = fmaf(a, u[3 * j + 2], t2);
        }
        t0 += __shfl_xor_sync(0xffffffffu, t0, 1);
        t1 += __shfl_xor_sync(0xffffffffu, t1, 1);
        t2 += __shfl_xor_sync(0xffffffffu, t2, 1);
        t0 += __shfl_xor_sync(0xffffffffu, t0, 2);
        t1 += __shfl_xor_sync(0xffffffffu, t1, 2);
        t2 += __shfl_xor_sync(0xffffffffu, t2, 2);
        if (!l4) {
            sT[row4 * 4 + 0] = t0;
            sT[row4 * 4 + 1] = t1;
            sT[row4 * 4 + 2] = t2;
            sT[row4 * 4 + 3] = 0.f;
        }
    }
    __syncthreads();

    // ---- P3b: h = elu(T @ W1), 2 adjacent cols x 16 rows per thread, packed STS.32
    {
        const int d2 = (tid & 63) * 2;
        const int q16 = tid >> 6;    // 0..3 -> rows q16*16..+15
        float wa0 = W1[d2],          wb0 = W1[d2 + 1];
        float wa1 = W1[HH + d2],     wb1 = W1[HH + d2 + 1];
        float wa2 = W1[2 * HH + d2], wb2 = W1[2 * HH + d2 + 1];
        uint* rh = (uint*)sHhi;
        uint* rl = (uint*)sHlo;
#pragma unroll
        for (int r = 0; r < 16; r++) {
            int row = q16 * 16 + r;
            float4 tt = *(const float4*)&sT[row * 4];
            float xa = elu1(fmaf(tt.x, wa0, fmaf(tt.y, wa1, tt.z * wa2)));
            float xb = elu1(fmaf(tt.x, wb0, fmaf(tt.y, wb1, tt.z * wb2)));
            uint h, l;
            split2(xa, xb, h, l);
            rh[row * (SH_STR / 2) + (d2 >> 1)] = h;
            rl[row * (SH_STR / 2) + (d2 >> 1)] = l;
        }
    }
    __syncthreads();

    // ---- P4: layer2 si/sj = h @ c2 (64 rows x 4 lanes); no barrier needed before P5
    {
        const uint* hh = (const uint*)(sHhi + row4 * SH_STR + l4 * 32);
        const uint* hl = (const uint*)(sHlo + row4 * SH_STR + l4 * 32);
        const float* cl = sC2l + l4 * 32;
        const float* cr = sC2r + l4 * 32;
        float s1 = 0.f, s2 = 0.f;
#pragma unroll
        for (int p = 0; p < 16; p++) {
            uint h2 = hh[p], l2 = hl[p];
            float h0 = bflo(h2) + bflo(l2);
            float h1 = bfhi(h2) + bfhi(l2);
            s1 = fmaf(h0, cl[2 * p], s1);     s2 = fmaf(h0, cr[2 * p], s2);
            s1 = fmaf(h1, cl[2 * p + 1], s1); s2 = fmaf(h1, cr[2 * p + 1], s2);
        }
        s1 += __shfl_xor_sync(0xffffffffu, s1, 1);
        s2 += __shfl_xor_sync(0xffffffffu, s2, 1);
        s1 += __shfl_xor_sync(0xffffffffu, s1, 2);
        s2 += __shfl_xor_sync(0xffffffffu, s2, 2);
        if (!l4) { sSi[row4] = s1; sSj[row4] = s2; }
    }

    // ---- P5: Wh2 = h @ W2, 8 warps m32n32, LDSM A-frags
    {
        float4 acc5[2][4];
#pragma unroll
        for (int h = 0; h < 2; h++)
#pragma unroll
            for (int f = 0; f < 4; f++) acc5[h][f] = make_float4(0.f, 0.f, 0.f, 0.f);
        const int arowl = mi2 * 32 + l7 + lb8 * 8;
        uint aHi0 = smaddr(sHhi) + arowl * (SH_STR * 2) + lb16 * 16;
        uint aLo0 = smaddr(sHlo) + arowl * (SH_STR * 2) + lb16 * 16;
#pragma unroll
        for (int ks = 0; ks < 8; ks++) {
            uint koff = ks * 32;
            uint4 ah[2], al[2];
#pragma unroll
            for (int h = 0; h < 2; h++) {
                ah[h] = ldsm4(aHi0 + h * (16 * SH_STR * 2) + koff);
                al[h] = ldsm4(aLo0 + h * (16 * SH_STR * 2) + koff);
            }
#pragma unroll
            for (int f = 0; f < 4; f++) {
                int nu = nb2 * 4 + f;
                uint4 q = g_W2B[(ks * 16 + nu) * 32 + lane];
#pragma unroll
                for (int h = 0; h < 2; h++) {
                    mma16816(acc5[h][f], ah[h].x, ah[h].y, ah[h].z, ah[h].w, q.x, q.y);
                    mma16816(acc5[h][f], ah[h].x, ah[h].y, ah[h].z, ah[h].w, q.z, q.w);
                    mma16816(acc5[h][f], al[h].x, al[h].y, al[h].z, al[h].w, q.x, q.y);
                }
            }
        }
        __syncthreads();   // all reads of sH done -> safe to overwrite region0 with Wh2
        uint* wh = (uint*)sHhi;
        uint* wl = (uint*)sHlo;
#pragma unroll
        for (int h = 0; h < 2; h++) {
            int r0 = mi2 * 32 + h * 16 + g;
#pragma unroll
            for (int f = 0; f < 4; f++) {
                int cu = (nb2 * 32 + f * 8 + 2 * t4) >> 1;
                float4 v = acc5[h][f];
                uint hw, lw;
                split2(v.x, v.y, hw, lw);
                wh[r0 * (SH_STR / 2) + cu] = hw;
                wl[r0 * (SH_STR / 2) + cu] = lw;
                split2(v.z, v.w, hw, lw);
                wh[(r0 + 8) * (SH_STR / 2) + cu] = hw;
                wl[(r0 + 8) * (SH_STR / 2) + cu] = lw;
            }
        }
    }
    __syncthreads();

    // ---- P6: softmax layer 2 -> attn bf16 hi/lo
    {
        float ev[16];
        softmax_core(ev, sSi, sSj, row4, l4);
        uint4 vh, vl;
        uint* ph = &vh.x;
        uint* pl = &vl.x;
#pragma unroll
        for (int p = 0; p < 4; p++) split2(ev[2 * p], ev[2 * p + 1], ph[p], pl[p]);
        *(uint4*)(atHi + row4 * (AT_STR * 2) + l4 * 32) = vh;
        *(uint4*)(atLo + row4 * (AT_STR * 2) + l4 * 32) = vl;
#pragma unroll
        for (int p = 0; p < 4; p++) split2(ev[8 + 2 * p], ev[9 + 2 * p], ph[p], pl[p]);
        *(uint4*)(atHi + row4 * (AT_STR * 2) + l4 * 32 + 16) = vh;
        *(uint4*)(atLo + row4 * (AT_STR * 2) + l4 * 32 + 16) = vl;
    }
    __syncthreads();

    // ---- P7: h2 = elu(attn2 @ Wh2), 8 warps m32n32; A via LDSM, B via LDSM.trans
    {
        float4 acc[2][4];
#pragma unroll
        for (int h = 0; h < 2; h++)
#pragma unroll
            for (int f = 0; f < 4; f++) acc[h][f] = make_float4(0.f, 0.f, 0.f, 0.f);
        const int arowl = mi2 * 32 + l7 + lb8 * 8;
        uint aHi0 = smaddr(atHi) + arowl * (AT_STR * 2) + lb16 * 16;
        uint aLo0 = smaddr(atLo) + arowl * (AT_STR * 2) + lb16 * 16;
        const int krl = l7 + lb8 * 8;
        uint bHi0 = smaddr(sHhi) + krl * (SH_STR * 2);
        uint bLo0 = smaddr(sHlo) + krl * (SH_STR * 2);
#pragma unroll
        for (int ks = 0; ks < 4; ks++) {
            uint4 ah[2], al[2];
#pragma unroll
            for (int h = 0; h < 2; h++) {
                ah[h] = ldsm4(aHi0 + h * (16 * AT_STR * 2) + ks * 32);
                al[h] = ldsm4(aLo0 + h * (16 * AT_STR * 2) + ks * 32);
            }
#pragma unroll
            for (int fp = 0; fp < 2; fp++) {
                int nu = nb2 * 4 + fp * 2 + lb16;
                uint boff = ks * 16 * (SH_STR * 2) + nu * 16;
                uint4 bh = ldsm4t(bHi0 + boff);
                uint4 bl = ldsm4t(bLo0 + boff);
                int f0 = fp * 2, f1 = fp * 2 + 1;
#pragma unroll
                for (int h = 0; h < 2; h++) {
                    mma16816(acc[h][f0], ah[h].x, ah[h].y, ah[h].z, ah[h].w, bh.x, bh.y);
                    mma16816(acc[h][f0], ah[h].x, ah[h].y, ah[h].z, ah[h].w, bl.x, bl.y);
                    mma16816(acc[h][f0], al[h].x, al[h].y, al[h].z, al[h].w, bh.x, bh.y);
                    mma16816(acc[h][f1], ah[h].x, ah[h].y, ah[h].z, ah[h].w, bh.z, bh.w);
                    mma16816(acc[h][f1], ah[h].x, ah[h].y, ah[h].z, ah[h].w, bl.z, bl.w);
                    mma16816(acc[h][f1], al[h].x, al[h].y, al[h].z, al[h].w, bh.z, bh.w);
                }
            }
        }
#pragma unroll
        for (int f = 0; f < 4; f++) {
            float p0 = -1e30f, p1 = -1e30f;
#pragma unroll
            for (int h = 0; h < 2; h++) {
                p0 = fmaxf(p0, fmaxf(elu1(acc[h][f].x), elu1(acc[h][f].z)));
                p1 = fmaxf(p1, fmaxf(elu1(acc[h][f].y), elu1(acc[h][f].w)));
            }
#pragma unroll
            for (int off = 4; off < 32; off <<= 1) {
                p0 = fmaxf(p0, __shfl_xor_sync(0xffffffffu, p0, off));
                p1 = fmaxf(p1, __shfl_xor_sync(0xffffffffu, p1, off));
            }
            if (lane < 4) {
                int c = nb2 * 32 + f * 8 + 2 * lane;
                *(float2*)&sPoolQ[mi2 * 128 + c] = make_float2(p0, p1);
            }
        }
    }
    __syncthreads();

    // ---- P7b: combine the two m-strips (sPool aliases dead sU)
    if (tid < 128) sPool[tid] = fmaxf(sPoolQ[tid], sPoolQ[128 + tid]);
    __syncthreads();

    // ---- P8: hidden = relu(pooled @ mw1 + mb1)  (32 cols x 8 lanes)
    {
        int col = tid >> 3, l8 = tid & 7;
        float acc = 0.f;
        const float* pp = sPool + l8 * 16;
#pragma unroll
        for (int k = 0; k < 16; k++) acc = fmaf(pp[k], mw1[(l8 * 16 + k) * 32 + col], acc);
        acc += __shfl_xor_sync(0xffffffffu, acc, 1);
        acc += __shfl_xor_sync(0xffffffffu, acc, 2);
        acc += __shfl_xor_sync(0xffffffffu, acc, 4);
        if (!l8) sR[col] = fmaxf(acc + mb1[col], 0.f);
    }
    __syncthreads();

    // ---- P9
    if (tid < 128) {
        float acc = mb2[tid];
#pragma unroll
        for (int m = 0; m < 32; m++) acc = fmaf(sR[m], mw2[m * HH + tid], acc);
        sO[tid] = fmaxf(acc, 0.f) + 1e-6f;
    }
    __syncthreads();

    // ---- P10
    if (tid < 2) {
        float s = 0.f;
        const float* p = sO + tid * 64;
#pragma unroll 8
        for (int j = 0; j < 64; j++) s += p[j];
        sSum[tid] = s;
    }
    __syncthreads();

    // ---- P11: normalize & write. power[B,A] then delta[B,A]
    if (tid < 128) {
        const float Bmax = 2.0f * 50.0f - 63.0f * 0.025f;  // 98.425
        const float PMAX = 1.0f;
        if (tid < 64) {
            out[(size_t)B * AA + (size_t)b * AA + tid] = Bmax * sO[tid] / (sSum[0] + 1e-6f);
        } else {
            out[(size_t)b * AA + (tid - 64)] = PMAX * sO[tid] / (sSum[1] + 1e-6f);
        }
    }
}

static const int SMEM_BYTES = 53248 + 994 * 4;   // 57224

extern "C" void kernel_launch(void* const* d_in, const int* in_sizes, int n_in,
                              void* d_out, int out_size) {
    const float* users = (const float*)d_in[0];
    const float* W1    = (const float*)d_in[1];
    const float* a1    = (const float*)d_in[2];
    const float* W2    = (const float*)d_in[3];
    const float* a2    = (const float*)d_in[4];
    const float* mw1   = (const float*)d_in[5];
    const float* mb1   = (const float*)d_in[6];
    const float* mw2   = (const float*)d_in[7];
    const float* mb2   = (const float*)d_in[8];
    float* out = (float*)d_out;

    int B = in_sizes[0] / (MM * INF_);

    cudaFuncSetAttribute(gat_kernel, cudaFuncAttributeMaxDynamicSharedMemorySize, SMEM_BYTES);

    precomp_kernel<<<1, 128>>>(W1, a1, W2, a2);
    gat_kernel<<<B, NT, SMEM_BYTES>>>(users, W1, W2, mw1, mb1, mw2, mb2, out, B);
}